// round 12
// baseline (speedup 1.0000x reference)
#include <cuda_runtime.h>
#include <cuda_fp16.h>
#include <math.h>
#include <stdint.h>

// Problem dims (fixed by the reference)
#define B_    4
#define N_    2048
#define D_    1024
#define H_    16
#define HD_   64
#define S_    11
#define M_    (B_ * N_)   // 8192

#define D4_0 0.4829629131445341f
#define D4_1 0.8365163037378079f
#define D4_2 0.2241438680420134f
#define D4_3 (-0.1294095225512604f)

// ---------------- scratch (static device globals; no allocation) -------------
__device__ __align__(256) __half g_gate[M_ * D_];
__device__ __align__(256) float g_logits[M_ * 256];     // h*11+s cols (176 used)
__device__ __align__(256) float g_kmag[M_ * H_];        // [m][h]
__device__ __align__(256) float g_vfield[B_ * H_ * N_ * HD_];  // raw v, [bh][n][hd]
__device__ __align__(256) __half g_outf [M_ * D_];      // [b][n][h*64+hd]
__device__ __align__(256) float g_cp[H_ * H_];          // softmaxed coupling

__device__ __align__(256) __half g_xhi[M_ * D_];
__device__ __align__(256) __half g_Ghi[M_ * D_];
__device__ __align__(256) __half g_Wkvhi[2 * D_ * D_];  // Wk, Wv hi
__device__ __align__(256) __half g_Wghi[D_ * D_];
__device__ __align__(256) __half g_Wohi[D_ * D_];
__device__ __align__(256) __half g_Weffhi[256 * D_];    // rows h*11+s (r<176), else 0

// ============================ PTX helpers ====================================
__device__ __forceinline__ uint32_t smem_u32(const void* p) {
    uint32_t a;
    asm("{ .reg .u64 t; cvta.to.shared.u64 t, %1; cvt.u32.u64 %0, t; }" : "=r"(a) : "l"(p));
    return a;
}

#define CP_ASYNC_16(sp, gp) \
    asm volatile("cp.async.cg.shared.global [%0], [%1], 16;" :: "r"(sp), "l"(gp) : "memory")
#define CP_COMMIT() asm volatile("cp.async.commit_group;" ::: "memory")
#define CP_WAIT(n)  asm volatile("cp.async.wait_group %0;" :: "n"(n) : "memory")

#define LDSM4(r0, r1, r2, r3, addr) \
    asm volatile("ldmatrix.sync.aligned.m8n8.x4.shared.b16 {%0,%1,%2,%3}, [%4];" \
        : "=r"(r0), "=r"(r1), "=r"(r2), "=r"(r3) : "r"(addr))
#define LDSM2(r0, r1, addr) \
    asm volatile("ldmatrix.sync.aligned.m8n8.x2.shared.b16 {%0,%1}, [%2];" \
        : "=r"(r0), "=r"(r1) : "r"(addr))

#define MMA16816(d, a, b) \
    asm volatile("mma.sync.aligned.m16n8k16.row.col.f32.f16.f16.f32 " \
        "{%0,%1,%2,%3}, {%4,%5,%6,%7}, {%8,%9}, {%0,%1,%2,%3};" \
        : "+f"((d)[0]), "+f"((d)[1]), "+f"((d)[2]), "+f"((d)[3]) \
        : "r"((a)[0]), "r"((a)[1]), "r"((a)[2]), "r"((a)[3]), "r"((b)[0]), "r"((b)[1]))

// ======================= fp16 tensor-core GEMM building blocks ===============
#define GBM 128
#define GBN 128
#define GBK 32
#define NSTAGE 4
#define ROWB   80
#define TILEB  (128 * ROWB)
#define STAGEB (2 * TILEB)
#define GEMM_SMEM (NSTAGE * STAGEB)

// ---- mega combo 1-pass GEMM: kmag | gate | logits | v in one launch ---------
// bx 0..7:   k -> reduce ||k|| per head -> g_kmag
// bx 8..15:  gate = sigmoid(x@Wg^T+bg) -> g_gate (fp16)
// bx 16..17: logits = x@Weff^T -> g_logits
// bx 18..25: v = x@Wv^T+bv -> g_vfield [bh][n][hd] (fp32, no kmag)
__global__ __launch_bounds__(256, 1)
void gemm_combo(const __half* __restrict__ xhi,
                const __half* __restrict__ Wk,
                const __half* __restrict__ Wg,
                const __half* __restrict__ Weff,
                const __half* __restrict__ Wv,
                const float* __restrict__ bk,
                const float* __restrict__ bg,
                const float* __restrict__ bv,
                float* __restrict__ Ckmag, __half* __restrict__ Cgate,
                float* __restrict__ Clog)
{
    constexpr int K = D_;
    extern __shared__ char smx[];
    const uint32_t sbase = smem_u32(smx);
    const int t = threadIdx.x;
    const int wid = t >> 5, lane = t & 31;
    const int wm = wid & 3, wn = wid >> 2;
    const int m0 = blockIdx.y * GBM;
    const int bx = blockIdx.x;

    const __half* Bp;
    if (bx < 8)       Bp = Wk   + (size_t)bx * 128 * K;
    else if (bx < 16) Bp = Wg   + (size_t)(bx - 8) * 128 * K;
    else if (bx < 18) Bp = Weff + (size_t)(bx - 16) * 128 * K;
    else              Bp = Wv   + (size_t)(bx - 18) * 128 * K;

    const int KITERS = K / GBK;

    float acc[2][8][4];
#pragma unroll
    for (int mi = 0; mi < 2; mi++)
#pragma unroll
        for (int ni = 0; ni < 8; ni++)
#pragma unroll
            for (int v = 0; v < 4; v++) acc[mi][ni][v] = 0.f;

    auto load_stage = [&](int stage, int kk) {
        const uint32_t sb = sbase + stage * STAGEB;
        const int r = t >> 2, c = t & 3;
#pragma unroll
        for (int j = 0; j < 4; j++) {
            const int tile = j >> 1;
            const int row  = ((j & 1) << 6) + r;
            const __half* g = (tile == 0) ? xhi : Bp;
            const int grow  = (tile == 0) ? (m0 + row) : row;
            CP_ASYNC_16(sb + tile * TILEB + row * ROWB + c * 16,
                        g + (size_t)grow * K + kk + c * 8);
        }
        CP_COMMIT();
    };

#pragma unroll
    for (int s = 0; s < NSTAGE - 1; s++) load_stage(s, s * GBK);

    const uint32_t a_off = (wm * 32 + (lane & 15)) * ROWB + (lane >> 4) * 16;
    const uint32_t b_off = (wn * 64 + (lane & 7)) * ROWB + ((lane >> 3) & 1) * 16;

    for (int it = 0; it < KITERS; it++) {
        CP_WAIT(NSTAGE - 2);
        __syncthreads();
        const int kload = it + NSTAGE - 1;
        if (kload < KITERS) load_stage(kload % NSTAGE, kload * GBK);
        else CP_COMMIT();                         // keep wait_group accounting exact

        const uint32_t st = sbase + (it % NSTAGE) * STAGEB;
#pragma unroll
        for (int ks = 0; ks < 2; ks++) {
            const uint32_t kb = ks * 32;
            uint32_t ah[2][4], bh[8][2];
#pragma unroll
            for (int mi = 0; mi < 2; mi++) {
                const uint32_t ar = st + a_off + mi * (16 * ROWB) + kb;
                LDSM4(ah[mi][0], ah[mi][1], ah[mi][2], ah[mi][3], ar);
            }
#pragma unroll
            for (int ni = 0; ni < 8; ni++) {
                const uint32_t br = st + TILEB + b_off + ni * (8 * ROWB) + kb;
                LDSM2(bh[ni][0], bh[ni][1], br);
            }
#pragma unroll
            for (int mi = 0; mi < 2; mi++)
#pragma unroll
                for (int ni = 0; ni < 8; ni++)
                    MMA16816(acc[mi][ni], ah[mi], bh[ni]);
        }
    }

    const int mrow = m0 + wm * 32 + (lane >> 2);
    const int ncl  = wn * 64 + (lane & 3) * 2;

    if (bx < 8) {
        // ||k||: this block's 128 cols = heads 2bx, 2bx+1; wn selects head
        float rs[2][2] = {{0.f, 0.f}, {0.f, 0.f}};
#pragma unroll
        for (int mi = 0; mi < 2; mi++)
#pragma unroll
            for (int ni = 0; ni < 8; ni++) {
                const int cl = bx * 128 + ncl + ni * 8;
                const float b0 = __ldg(&bk[cl]);
                const float b1 = __ldg(&bk[cl + 1]);
                const float v0 = acc[mi][ni][0] + b0, v1 = acc[mi][ni][1] + b1;
                const float v2 = acc[mi][ni][2] + b0, v3 = acc[mi][ni][3] + b1;
                rs[mi][0] += v0 * v0 + v1 * v1;
                rs[mi][1] += v2 * v2 + v3 * v3;
            }
#pragma unroll
        for (int mi = 0; mi < 2; mi++)
#pragma unroll
            for (int hf = 0; hf < 2; hf++) {
                rs[mi][hf] += __shfl_xor_sync(0xffffffffu, rs[mi][hf], 1);
                rs[mi][hf] += __shfl_xor_sync(0xffffffffu, rs[mi][hf], 2);
            }
        if ((lane & 3) == 0) {
            const int head = bx * 2 + wn;
#pragma unroll
            for (int mi = 0; mi < 2; mi++) {
                const int r0 = mrow + mi * 16;
                Ckmag[(size_t)r0 * H_ + head]       = sqrtf(rs[mi][0]);
                Ckmag[(size_t)(r0 + 8) * H_ + head] = sqrtf(rs[mi][1]);
            }
        }
    } else if (bx < 16) {
#pragma unroll
        for (int mi = 0; mi < 2; mi++)
#pragma unroll
            for (int ni = 0; ni < 8; ni++) {
                const int cl = (bx - 8) * 128 + ncl + ni * 8;
                const float b0 = __ldg(&bg[cl]);
                const float b1 = __ldg(&bg[cl + 1]);
                float v0 = acc[mi][ni][0] + b0, v1 = acc[mi][ni][1] + b1;
                float v2 = acc[mi][ni][2] + b0, v3 = acc[mi][ni][3] + b1;
                v0 = 1.f / (1.f + __expf(-v0)); v1 = 1.f / (1.f + __expf(-v1));
                v2 = 1.f / (1.f + __expf(-v2)); v3 = 1.f / (1.f + __expf(-v3));
                const int r0 = mrow + mi * 16;
                *(__half2*)(Cgate + (size_t)r0 * D_ + cl)       = __floats2half2_rn(v0, v1);
                *(__half2*)(Cgate + (size_t)(r0 + 8) * D_ + cl) = __floats2half2_rn(v2, v3);
            }
    } else if (bx < 18) {
#pragma unroll
        for (int mi = 0; mi < 2; mi++)
#pragma unroll
            for (int ni = 0; ni < 8; ni++) {
                const int cl = (bx - 16) * 128 + ncl + ni * 8;
                const int r0 = mrow + mi * 16;
                *(float2*)(Clog + (size_t)r0 * 256 + cl) =
                    make_float2(acc[mi][ni][0], acc[mi][ni][1]);
                *(float2*)(Clog + (size_t)(r0 + 8) * 256 + cl) =
                    make_float2(acc[mi][ni][2], acc[mi][ni][3]);
            }
    } else {
        // v region: scatter raw v (+bias) into g_vfield [bh][n][hd]
        const int head = (bx - 18) * 2 + wn;
        const int hdb  = (lane & 3) * 2;
#pragma unroll
        for (int mi = 0; mi < 2; mi++) {
            const int r0 = mrow + mi * 16;
            const int r1 = r0 + 8;
            float* f0 = g_vfield + (((size_t)((r0 >> 11) * H_ + head) * N_ + (r0 & (N_ - 1))) * HD_);
            float* f1 = g_vfield + (((size_t)((r1 >> 11) * H_ + head) * N_ + (r1 & (N_ - 1))) * HD_);
#pragma unroll
            for (int ni = 0; ni < 8; ni++) {
                const int hd = hdb + ni * 8;
                const int cg = head * 64 + hd;
                const float b0 = __ldg(&bv[cg]);
                const float b1 = __ldg(&bv[cg + 1]);
                *(float2*)(f0 + hd) = make_float2(acc[mi][ni][0] + b0, acc[mi][ni][1] + b1);
                *(float2*)(f1 + hd) = make_float2(acc[mi][ni][2] + b0, acc[mi][ni][3] + b1);
            }
        }
    }
}

// ---- out GEMM (1-pass): out = Ghi @ Wohi^T + bo ------------------------------
__global__ __launch_bounds__(256, 1)
void gemm_out(const __half* __restrict__ Ahi, const __half* __restrict__ Bhi,
              const float* __restrict__ bias, float* __restrict__ C)
{
    constexpr int K = D_;
    extern __shared__ char smx[];
    const uint32_t sbase = smem_u32(smx);
    const int t = threadIdx.x;
    const int wid = t >> 5, lane = t & 31;
    const int wm = wid & 3, wn = wid >> 2;
    const int m0 = blockIdx.y * GBM;
    const int n0 = blockIdx.x * GBN;
    const int KITERS = K / GBK;

    float acc[2][8][4];
#pragma unroll
    for (int mi = 0; mi < 2; mi++)
#pragma unroll
        for (int ni = 0; ni < 8; ni++)
#pragma unroll
            for (int v = 0; v < 4; v++) acc[mi][ni][v] = 0.f;

    auto load_stage = [&](int stage, int kk) {
        const uint32_t sb = sbase + stage * STAGEB;
        const int r = t >> 2, c = t & 3;
#pragma unroll
        for (int j = 0; j < 4; j++) {
            const int tile = j >> 1;
            const int row  = ((j & 1) << 6) + r;
            const __half* g = (tile == 0) ? Ahi : Bhi;
            const int grow  = (tile == 0) ? (m0 + row) : (n0 + row);
            CP_ASYNC_16(sb + tile * TILEB + row * ROWB + c * 16,
                        g + (size_t)grow * K + kk + c * 8);
        }
        CP_COMMIT();
    };

#pragma unroll
    for (int s = 0; s < NSTAGE - 1; s++) load_stage(s, s * GBK);

    const uint32_t a_off = (wm * 32 + (lane & 15)) * ROWB + (lane >> 4) * 16;
    const uint32_t b_off = (wn * 64 + (lane & 7)) * ROWB + ((lane >> 3) & 1) * 16;

    for (int it = 0; it < KITERS; it++) {
        CP_WAIT(NSTAGE - 2);
        __syncthreads();
        const int kload = it + NSTAGE - 1;
        if (kload < KITERS) load_stage(kload % NSTAGE, kload * GBK);
        else CP_COMMIT();

        const uint32_t st = sbase + (it % NSTAGE) * STAGEB;
#pragma unroll
        for (int ks = 0; ks < 2; ks++) {
            const uint32_t kb = ks * 32;
            uint32_t ah[2][4], bh[8][2];
#pragma unroll
            for (int mi = 0; mi < 2; mi++) {
                const uint32_t ar = st + a_off + mi * (16 * ROWB) + kb;
                LDSM4(ah[mi][0], ah[mi][1], ah[mi][2], ah[mi][3], ar);
            }
#pragma unroll
            for (int ni = 0; ni < 8; ni++) {
                const uint32_t br = st + TILEB + b_off + ni * (8 * ROWB) + kb;
                LDSM2(bh[ni][0], bh[ni][1], br);
            }
#pragma unroll
            for (int mi = 0; mi < 2; mi++)
#pragma unroll
                for (int ni = 0; ni < 8; ni++)
                    MMA16816(acc[mi][ni], ah[mi], bh[ni]);
        }
    }

    const int mrow = m0 + wm * 32 + (lane >> 2);
    const int ncol = n0 + wn * 64 + (lane & 3) * 2;
#pragma unroll
    for (int mi = 0; mi < 2; mi++)
#pragma unroll
        for (int ni = 0; ni < 8; ni++) {
            const int cbase = ncol + ni * 8;
            const float b0 = __ldg(&bias[cbase]);
            const float b1 = __ldg(&bias[cbase + 1]);
            const int r0 = mrow + mi * 16;
            *(float2*)(C + (size_t)r0 * D_ + cbase) =
                make_float2(acc[mi][ni][0] + b0, acc[mi][ni][1] + b1);
            *(float2*)(C + (size_t)(r0 + 8) * D_ + cbase) =
                make_float2(acc[mi][ni][2] + b0, acc[mi][ni][3] + b1);
        }
}

// ---------------- fused hi-only splits: x, Wkv, Wg, Wo + coupling softmax -----
#define SPLIT_X   (M_ * D_ / 4)
#define SPLIT_KV  (2 * D_ * D_ / 4)
#define SPLIT_W   (D_ * D_ / 4)
#define SPLIT_TOT (SPLIT_X + SPLIT_KV + 2 * SPLIT_W)
#define SPLIT_BLKS ((SPLIT_TOT + 255) / 256)

__global__ __launch_bounds__(256)
void fused_split_kernel(const float4* __restrict__ x, const float4* __restrict__ Wkv,
                        const float4* __restrict__ Wg, const float4* __restrict__ Wo,
                        const float* __restrict__ fc)
{
    if (blockIdx.x == SPLIT_BLKS) {
        // coupling softmax: one block, 16 threads active
        const int tid = threadIdx.x;
        if (tid < H_) {
            float row[H_];
            float mx = -1e30f;
#pragma unroll
            for (int j = 0; j < H_; j++) { row[j] = __ldg(&fc[tid * H_ + j]); mx = fmaxf(mx, row[j]); }
            float sum = 0.f;
#pragma unroll
            for (int j = 0; j < H_; j++) { row[j] = __expf(row[j] - mx); sum += row[j]; }
            const float inv = 1.f / sum;
#pragma unroll
            for (int j = 0; j < H_; j++) g_cp[tid * H_ + j] = row[j] * inv;
        }
        return;
    }
    const int i = blockIdx.x * blockDim.x + threadIdx.x;
    if (i >= SPLIT_TOT) return;
    const float4* src;
    __half2* dst;
    int j;
    if (i < SPLIT_X)                          { j = i;                          src = x;   dst = (__half2*)g_xhi; }
    else if (i < SPLIT_X + SPLIT_KV)          { j = i - SPLIT_X;                src = Wkv; dst = (__half2*)g_Wkvhi; }
    else if (i < SPLIT_X + SPLIT_KV + SPLIT_W){ j = i - SPLIT_X - SPLIT_KV;     src = Wg;  dst = (__half2*)g_Wghi; }
    else                                      { j = i - SPLIT_X - SPLIT_KV - SPLIT_W; src = Wo; dst = (__half2*)g_Wohi; }
    const float4 v = src[j];
    dst[2 * j]     = __halves2half2(__float2half(v.x), __float2half(v.y));
    dst[2 * j + 1] = __halves2half2(__float2half(v.z), __float2half(v.w));
}

// ---------------- Weff = Wqs @ Wq (per head), fp32 -> fp16 --------------------
__global__ __launch_bounds__(256)
void weff_kernel(const float* __restrict__ Wqkv, const float* __restrict__ Wqs,
                 __half* __restrict__ Weff)
{
    const int r = blockIdx.y;
    const int k = blockIdx.x * 256 + threadIdx.x;
    float acc = 0.f;
    if (r < 176) {
        const int h = r / 11, s = r % 11;
        const float* wq = Wqkv + (size_t)(h * 64) * D_ + k;
        const float* ws = Wqs + s * HD_;
#pragma unroll 16
        for (int d = 0; d < 64; d++)
            acc = fmaf(__ldg(&ws[d]), __ldg(&wq[(size_t)d * D_]), acc);
    }
    Weff[(size_t)r * D_ + k] = __float2half(acc);
}

// -------- stage: causal multiscale dilated D4 conv + fused gains softmax ------
// smem: slab [2048][16] fp32 (128 KB) + gains [2048][11] fp32 (88 KB) = 216 KB
#define CONV_SLAB_FLOATS (N_ * 16)
#define CONV_SMEM ((CONV_SLAB_FLOATS + N_ * S_) * 4)   // 221184 B

__global__ __launch_bounds__(512)
void conv_kernel3(const float* __restrict__ logits,
                  const float* __restrict__ scale_gain)
{
    extern __shared__ float smem_c[];
    float* slab   = smem_c;                    // [2048][16]
    float* gain_s = smem_c + CONV_SLAB_FLOATS; // [2048][11]

    const int bh  = blockIdx.y;
    const int hd0 = blockIdx.x * 16;
    const int t   = threadIdx.x;
    const int b   = bh >> 4, h = bh & 15;

    // scale_gain[s][h] for this head
    float sg[S_];
#pragma unroll
    for (int s = 0; s < S_; s++) sg[s] = __ldg(&scale_gain[s * H_ + h]);

    // phase 1a: slab load (field = v * kmag)
    const float* fb = g_vfield + (size_t)bh * N_ * HD_;
#pragma unroll
    for (int i = 0; i < 16; i++) {
        const int idx = i * 512 + t;
        const int n = idx >> 2, c = idx & 3;
        float4 v = *(const float4*)(fb + (size_t)n * HD_ + hd0 + c * 4);
        const float km = __ldg(&g_kmag[((size_t)(b * N_ + n)) * H_ + h]);
        v.x *= km; v.y *= km; v.z *= km; v.w *= km;
        ((float4*)slab)[idx] = v;
    }
    // phase 1b: gains softmax (4 n-rows per thread) straight from logits
#pragma unroll
    for (int i = 0; i < 4; i++) {
        const int n = t + i * 512;
        const float* lp = logits + ((size_t)(b * N_ + n)) * 256 + h * S_;
        float l[S_];
        float mx = -1e30f;
#pragma unroll
        for (int s = 0; s < S_; s++) {
            l[s] = __ldg(&lp[s]) + sg[s];
            mx = fmaxf(mx, l[s]);
        }
        float sum = 0.f;
#pragma unroll
        for (int s = 0; s < S_; s++) { l[s] = __expf(l[s] - mx); sum += l[s]; }
        const float inv = 1.f / sum;
#pragma unroll
        for (int s = 0; s < S_; s++) gain_s[n * S_ + s] = l[s] * inv;
    }
    __syncthreads();

    const int hd = t & 15, nb = t >> 4;
    __half* ob = g_outf + (size_t)b * N_ * D_ + h * HD_ + hd0 + hd;
    for (int ni = 0; ni < 64; ni++) {
        const int n = ni * 32 + nb;
        const float* gp = gain_s + n * S_;

        float acc = D4_3 * slab[n * 16 + hd];
#pragma unroll
        for (int j = 0; j < S_; j++) {
            const int d = 1 << j;
            const float g = gp[j];
            const int s3 = n - 3 * d, s2 = n - 2 * d, s1 = n - d;
            if (s3 >= 0) acc = fmaf(g * D4_0, slab[s3 * 16 + hd], acc);
            if (s2 >= 0) acc = fmaf(g * D4_1, slab[s2 * 16 + hd], acc);
            if (s1 >= 0) acc = fmaf(g * D4_2, slab[s1 * 16 + hd], acc);
        }
        ob[(size_t)n * D_] = __float2half(acc);
    }
}

// -------- stage: head coupling + gate; emits fp16 G (precomputed cp) ----------
__global__ __launch_bounds__(256)
void couple_gate_kernel()
{
    __shared__ float sf[D_];
    __shared__ float cps[H_ * H_];

    const int bn = blockIdx.x;
    const int tid = threadIdx.x;

    cps[tid] = g_cp[tid];                     // 256 threads, one coalesced load
    const __half2* orow = (const __half2*)(g_outf + (size_t)bn * D_);
#pragma unroll
    for (int r = 0; r < 2; r++) {
        const int i = tid + r * 256;
        const float2 f = __half22float2(orow[i]);
        sf[2 * i] = f.x; sf[2 * i + 1] = f.y;
    }
    __syncthreads();

    const size_t grow = (size_t)bn * D_;
#pragma unroll
    for (int r = 0; r < 4; r++) {
        const int idx = tid + r * 256;
        const int i = idx >> 6, hd = idx & 63;
        float acc = 0.f;
#pragma unroll
        for (int j = 0; j < H_; j++) acc = fmaf(cps[i * 16 + j], sf[j * HD_ + hd], acc);
        g_Ghi[grow + idx] = __float2half(acc * __half2float(g_gate[grow + idx]));
    }
}

// ------------------------------- launch --------------------------------------
extern "C" void kernel_launch(void* const* d_in, const int* in_sizes, int n_in,
                              void* d_out, int out_size)
{
    const float* x    = (const float*)d_in[0];
    const float* Wqkv = (const float*)d_in[1];
    const float* bqkv = (const float*)d_in[2];
    const float* Wo   = (const float*)d_in[3];
    const float* bo   = (const float*)d_in[4];
    const float* Wg   = (const float*)d_in[5];
    const float* bg   = (const float*)d_in[6];
    const float* scale_gain = (const float*)d_in[7];
    const float* Wqs  = (const float*)d_in[8];
    const float* fc   = (const float*)d_in[9];
    float* out = (float*)d_out;

    float *p_logits, *p_kmag;
    __half *p_gate, *p_xhi, *p_Ghi, *p_Wkvhi, *p_Wghi, *p_Wohi, *p_Weff;
    cudaGetSymbolAddress((void**)&p_gate, g_gate);
    cudaGetSymbolAddress((void**)&p_logits, g_logits);
    cudaGetSymbolAddress((void**)&p_kmag, g_kmag);
    cudaGetSymbolAddress((void**)&p_xhi, g_xhi);
    cudaGetSymbolAddress((void**)&p_Ghi, g_Ghi);
    cudaGetSymbolAddress((void**)&p_Wkvhi, g_Wkvhi);
    cudaGetSymbolAddress((void**)&p_Wghi, g_Wghi);
    cudaGetSymbolAddress((void**)&p_Wohi, g_Wohi);
    cudaGetSymbolAddress((void**)&p_Weff, g_Weffhi);

    cudaFuncSetAttribute(gemm_combo, cudaFuncAttributeMaxDynamicSharedMemorySize, GEMM_SMEM);
    cudaFuncSetAttribute(gemm_out,   cudaFuncAttributeMaxDynamicSharedMemorySize, GEMM_SMEM);
    cudaFuncSetAttribute(conv_kernel3, cudaFuncAttributeMaxDynamicSharedMemorySize, CONV_SMEM);

    // 0) fused hi-only splits (+ coupling softmax block) + Weff precompute
    fused_split_kernel<<<SPLIT_BLKS + 1, 256>>>(
        (const float4*)x, (const float4*)(Wqkv + (size_t)D_ * D_),
        (const float4*)Wg, (const float4*)Wo, fc);
    {
        dim3 wgrid(D_ / 256, 256);
        weff_kernel<<<wgrid, 256>>>(Wqkv, Wqs, p_Weff);
    }

    // 1) mega combo: kmag | gate | logits | v  (all 1-pass, one launch)
    {
        dim3 grid(26, M_ / GBM);
        gemm_combo<<<grid, 256, GEMM_SMEM>>>(
            p_xhi, p_Wkvhi, p_Wghi, p_Weff, p_Wkvhi + (size_t)D_ * D_,
            bqkv + D_, bg, bqkv + 2 * D_,
            p_kmag, p_gate, p_logits);
    }
    // 2) multiscale causal conv + fused gains softmax -> outf fp16
    {
        dim3 grid(HD_ / 16, B_ * H_);
        conv_kernel3<<<grid, 512, CONV_SMEM>>>(p_logits, scale_gain);
    }
    // 3) head coupling + gate -> Ghi (fp16)
    couple_gate_kernel<<<B_ * N_, 256>>>();

    // 4) out = Ghi @ Wohi^T + bo   (1-pass)
    {
        dim3 grid(D_ / GBN, M_ / GBM);
        gemm_out<<<grid, 256, GEMM_SMEM>>>(p_Ghi, p_Wohi, bo, out);
    }
}

// round 13
// speedup vs baseline: 1.0826x; 1.0826x over previous
#include <cuda_runtime.h>
#include <cuda_fp16.h>
#include <math.h>
#include <stdint.h>

// Problem dims (fixed by the reference)
#define B_    4
#define N_    2048
#define D_    1024
#define H_    16
#define HD_   64
#define S_    11
#define M_    (B_ * N_)   // 8192

#define D4_0 0.4829629131445341f
#define D4_1 0.8365163037378079f
#define D4_2 0.2241438680420134f
#define D4_3 (-0.1294095225512604f)

// ---------------- scratch (static device globals; no allocation) -------------
__device__ __align__(256) __half g_gate[M_ * D_];
__device__ __align__(256) float g_logits[M_ * 256];     // h*11+s cols (176 used)
__device__ __align__(256) float g_kmag[M_ * H_];        // [m][h]
__device__ __align__(256) __half g_vfield[B_ * H_ * N_ * HD_]; // raw v, [bh][n][hd]
__device__ __align__(256) float g_gains[B_ * H_ * N_ * S_];    // [bh][n][s]
__device__ __align__(256) __half g_outf [M_ * D_];      // [b][n][h*64+hd]
__device__ __align__(256) float g_cp[H_ * H_];          // softmaxed coupling

__device__ __align__(256) __half g_xhi[M_ * D_];
__device__ __align__(256) __half g_Ghi[M_ * D_];
__device__ __align__(256) __half g_Wkvhi[2 * D_ * D_];  // Wk, Wv hi
__device__ __align__(256) __half g_Wghi[D_ * D_];
__device__ __align__(256) __half g_Wohi[D_ * D_];
__device__ __align__(256) __half g_Weffhi[256 * D_];    // rows h*11+s (r<176), else 0

// ============================ PTX helpers ====================================
__device__ __forceinline__ uint32_t smem_u32(const void* p) {
    uint32_t a;
    asm("{ .reg .u64 t; cvta.to.shared.u64 t, %1; cvt.u32.u64 %0, t; }" : "=r"(a) : "l"(p));
    return a;
}

#define CP_ASYNC_16(sp, gp) \
    asm volatile("cp.async.cg.shared.global [%0], [%1], 16;" :: "r"(sp), "l"(gp) : "memory")
#define CP_COMMIT() asm volatile("cp.async.commit_group;" ::: "memory")
#define CP_WAIT(n)  asm volatile("cp.async.wait_group %0;" :: "n"(n) : "memory")

#define LDSM4(r0, r1, r2, r3, addr) \
    asm volatile("ldmatrix.sync.aligned.m8n8.x4.shared.b16 {%0,%1,%2,%3}, [%4];" \
        : "=r"(r0), "=r"(r1), "=r"(r2), "=r"(r3) : "r"(addr))
#define LDSM2(r0, r1, addr) \
    asm volatile("ldmatrix.sync.aligned.m8n8.x2.shared.b16 {%0,%1}, [%2];" \
        : "=r"(r0), "=r"(r1) : "r"(addr))

#define MMA16816(d, a, b) \
    asm volatile("mma.sync.aligned.m16n8k16.row.col.f32.f16.f16.f32 " \
        "{%0,%1,%2,%3}, {%4,%5,%6,%7}, {%8,%9}, {%0,%1,%2,%3};" \
        : "+f"((d)[0]), "+f"((d)[1]), "+f"((d)[2]), "+f"((d)[3]) \
        : "r"((a)[0]), "r"((a)[1]), "r"((a)[2]), "r"((a)[3]), "r"((b)[0]), "r"((b)[1]))

// ======================= fp16 tensor-core GEMM building blocks ===============
#define GBM 128
#define GBN 128
#define GBK 32
#define NSTAGE 4
#define ROWB   80
#define TILEB  (128 * ROWB)
#define STAGEB (2 * TILEB)
#define GEMM_SMEM (NSTAGE * STAGEB)

// ---- mega combo 1-pass GEMM: kmag | gate | logits | v in one launch ---------
// bx 0..7:   k -> reduce ||k|| per head -> g_kmag
// bx 8..15:  gate = sigmoid(x@Wg^T+bg) -> g_gate (fp16)
// bx 16..17: logits = x@Weff^T -> g_logits
// bx 18..25: v = x@Wv^T+bv -> g_vfield [bh][n][hd] (fp16, no kmag)
__global__ __launch_bounds__(256, 1)
void gemm_combo(const __half* __restrict__ xhi,
                const __half* __restrict__ Wk,
                const __half* __restrict__ Wg,
                const __half* __restrict__ Weff,
                const __half* __restrict__ Wv,
                const float* __restrict__ bk,
                const float* __restrict__ bg,
                const float* __restrict__ bv,
                float* __restrict__ Ckmag, __half* __restrict__ Cgate,
                float* __restrict__ Clog)
{
    constexpr int K = D_;
    extern __shared__ char smx[];
    const uint32_t sbase = smem_u32(smx);
    const int t = threadIdx.x;
    const int wid = t >> 5, lane = t & 31;
    const int wm = wid & 3, wn = wid >> 2;
    const int m0 = blockIdx.y * GBM;
    const int bx = blockIdx.x;

    const __half* Bp;
    if (bx < 8)       Bp = Wk   + (size_t)bx * 128 * K;
    else if (bx < 16) Bp = Wg   + (size_t)(bx - 8) * 128 * K;
    else if (bx < 18) Bp = Weff + (size_t)(bx - 16) * 128 * K;
    else              Bp = Wv   + (size_t)(bx - 18) * 128 * K;

    const int KITERS = K / GBK;

    float acc[2][8][4];
#pragma unroll
    for (int mi = 0; mi < 2; mi++)
#pragma unroll
        for (int ni = 0; ni < 8; ni++)
#pragma unroll
            for (int v = 0; v < 4; v++) acc[mi][ni][v] = 0.f;

    auto load_stage = [&](int stage, int kk) {
        const uint32_t sb = sbase + stage * STAGEB;
        const int r = t >> 2, c = t & 3;
#pragma unroll
        for (int j = 0; j < 4; j++) {
            const int tile = j >> 1;
            const int row  = ((j & 1) << 6) + r;
            const __half* g = (tile == 0) ? xhi : Bp;
            const int grow  = (tile == 0) ? (m0 + row) : row;
            CP_ASYNC_16(sb + tile * TILEB + row * ROWB + c * 16,
                        g + (size_t)grow * K + kk + c * 8);
        }
        CP_COMMIT();
    };

#pragma unroll
    for (int s = 0; s < NSTAGE - 1; s++) load_stage(s, s * GBK);

    const uint32_t a_off = (wm * 32 + (lane & 15)) * ROWB + (lane >> 4) * 16;
    const uint32_t b_off = (wn * 64 + (lane & 7)) * ROWB + ((lane >> 3) & 1) * 16;

    for (int it = 0; it < KITERS; it++) {
        CP_WAIT(NSTAGE - 2);
        __syncthreads();
        const int kload = it + NSTAGE - 1;
        if (kload < KITERS) load_stage(kload % NSTAGE, kload * GBK);
        else CP_COMMIT();                         // keep wait_group accounting exact

        const uint32_t st = sbase + (it % NSTAGE) * STAGEB;
#pragma unroll
        for (int ks = 0; ks < 2; ks++) {
            const uint32_t kb = ks * 32;
            uint32_t ah[2][4], bh[8][2];
#pragma unroll
            for (int mi = 0; mi < 2; mi++) {
                const uint32_t ar = st + a_off + mi * (16 * ROWB) + kb;
                LDSM4(ah[mi][0], ah[mi][1], ah[mi][2], ah[mi][3], ar);
            }
#pragma unroll
            for (int ni = 0; ni < 8; ni++) {
                const uint32_t br = st + TILEB + b_off + ni * (8 * ROWB) + kb;
                LDSM2(bh[ni][0], bh[ni][1], br);
            }
#pragma unroll
            for (int mi = 0; mi < 2; mi++)
#pragma unroll
                for (int ni = 0; ni < 8; ni++)
                    MMA16816(acc[mi][ni], ah[mi], bh[ni]);
        }
    }

    const int mrow = m0 + wm * 32 + (lane >> 2);
    const int ncl  = wn * 64 + (lane & 3) * 2;

    if (bx < 8) {
        // ||k||: this block's 128 cols = heads 2bx, 2bx+1; wn selects head
        float rs[2][2] = {{0.f, 0.f}, {0.f, 0.f}};
#pragma unroll
        for (int mi = 0; mi < 2; mi++)
#pragma unroll
            for (int ni = 0; ni < 8; ni++) {
                const int cl = bx * 128 + ncl + ni * 8;
                const float b0 = __ldg(&bk[cl]);
                const float b1 = __ldg(&bk[cl + 1]);
                const float v0 = acc[mi][ni][0] + b0, v1 = acc[mi][ni][1] + b1;
                const float v2 = acc[mi][ni][2] + b0, v3 = acc[mi][ni][3] + b1;
                rs[mi][0] += v0 * v0 + v1 * v1;
                rs[mi][1] += v2 * v2 + v3 * v3;
            }
#pragma unroll
        for (int mi = 0; mi < 2; mi++)
#pragma unroll
            for (int hf = 0; hf < 2; hf++) {
                rs[mi][hf] += __shfl_xor_sync(0xffffffffu, rs[mi][hf], 1);
                rs[mi][hf] += __shfl_xor_sync(0xffffffffu, rs[mi][hf], 2);
            }
        if ((lane & 3) == 0) {
            const int head = bx * 2 + wn;
#pragma unroll
            for (int mi = 0; mi < 2; mi++) {
                const int r0 = mrow + mi * 16;
                Ckmag[(size_t)r0 * H_ + head]       = sqrtf(rs[mi][0]);
                Ckmag[(size_t)(r0 + 8) * H_ + head] = sqrtf(rs[mi][1]);
            }
        }
    } else if (bx < 16) {
#pragma unroll
        for (int mi = 0; mi < 2; mi++)
#pragma unroll
            for (int ni = 0; ni < 8; ni++) {
                const int cl = (bx - 8) * 128 + ncl + ni * 8;
                const float b0 = __ldg(&bg[cl]);
                const float b1 = __ldg(&bg[cl + 1]);
                float v0 = acc[mi][ni][0] + b0, v1 = acc[mi][ni][1] + b1;
                float v2 = acc[mi][ni][2] + b0, v3 = acc[mi][ni][3] + b1;
                v0 = 1.f / (1.f + __expf(-v0)); v1 = 1.f / (1.f + __expf(-v1));
                v2 = 1.f / (1.f + __expf(-v2)); v3 = 1.f / (1.f + __expf(-v3));
                const int r0 = mrow + mi * 16;
                *(__half2*)(Cgate + (size_t)r0 * D_ + cl)       = __floats2half2_rn(v0, v1);
                *(__half2*)(Cgate + (size_t)(r0 + 8) * D_ + cl) = __floats2half2_rn(v2, v3);
            }
    } else if (bx < 18) {
#pragma unroll
        for (int mi = 0; mi < 2; mi++)
#pragma unroll
            for (int ni = 0; ni < 8; ni++) {
                const int cl = (bx - 16) * 128 + ncl + ni * 8;
                const int r0 = mrow + mi * 16;
                *(float2*)(Clog + (size_t)r0 * 256 + cl) =
                    make_float2(acc[mi][ni][0], acc[mi][ni][1]);
                *(float2*)(Clog + (size_t)(r0 + 8) * 256 + cl) =
                    make_float2(acc[mi][ni][2], acc[mi][ni][3]);
            }
    } else {
        // v region: scatter raw v (+bias) into g_vfield [bh][n][hd] fp16
        const int head = (bx - 18) * 2 + wn;
        const int hdb  = (lane & 3) * 2;
#pragma unroll
        for (int mi = 0; mi < 2; mi++) {
            const int r0 = mrow + mi * 16;
            const int r1 = r0 + 8;
            __half* f0 = g_vfield + (((size_t)((r0 >> 11) * H_ + head) * N_ + (r0 & (N_ - 1))) * HD_);
            __half* f1 = g_vfield + (((size_t)((r1 >> 11) * H_ + head) * N_ + (r1 & (N_ - 1))) * HD_);
#pragma unroll
            for (int ni = 0; ni < 8; ni++) {
                const int hd = hdb + ni * 8;
                const int cg = head * 64 + hd;
                const float b0 = __ldg(&bv[cg]);
                const float b1 = __ldg(&bv[cg + 1]);
                *(__half2*)(f0 + hd) = __floats2half2_rn(acc[mi][ni][0] + b0, acc[mi][ni][1] + b1);
                *(__half2*)(f1 + hd) = __floats2half2_rn(acc[mi][ni][2] + b0, acc[mi][ni][3] + b1);
            }
        }
    }
}

// ---- out GEMM (1-pass): out = Ghi @ Wohi^T + bo ------------------------------
__global__ __launch_bounds__(256, 1)
void gemm_out(const __half* __restrict__ Ahi, const __half* __restrict__ Bhi,
              const float* __restrict__ bias, float* __restrict__ C)
{
    constexpr int K = D_;
    extern __shared__ char smx[];
    const uint32_t sbase = smem_u32(smx);
    const int t = threadIdx.x;
    const int wid = t >> 5, lane = t & 31;
    const int wm = wid & 3, wn = wid >> 2;
    const int m0 = blockIdx.y * GBM;
    const int n0 = blockIdx.x * GBN;
    const int KITERS = K / GBK;

    float acc[2][8][4];
#pragma unroll
    for (int mi = 0; mi < 2; mi++)
#pragma unroll
        for (int ni = 0; ni < 8; ni++)
#pragma unroll
            for (int v = 0; v < 4; v++) acc[mi][ni][v] = 0.f;

    auto load_stage = [&](int stage, int kk) {
        const uint32_t sb = sbase + stage * STAGEB;
        const int r = t >> 2, c = t & 3;
#pragma unroll
        for (int j = 0; j < 4; j++) {
            const int tile = j >> 1;
            const int row  = ((j & 1) << 6) + r;
            const __half* g = (tile == 0) ? Ahi : Bhi;
            const int grow  = (tile == 0) ? (m0 + row) : (n0 + row);
            CP_ASYNC_16(sb + tile * TILEB + row * ROWB + c * 16,
                        g + (size_t)grow * K + kk + c * 8);
        }
        CP_COMMIT();
    };

#pragma unroll
    for (int s = 0; s < NSTAGE - 1; s++) load_stage(s, s * GBK);

    const uint32_t a_off = (wm * 32 + (lane & 15)) * ROWB + (lane >> 4) * 16;
    const uint32_t b_off = (wn * 64 + (lane & 7)) * ROWB + ((lane >> 3) & 1) * 16;

    for (int it = 0; it < KITERS; it++) {
        CP_WAIT(NSTAGE - 2);
        __syncthreads();
        const int kload = it + NSTAGE - 1;
        if (kload < KITERS) load_stage(kload % NSTAGE, kload * GBK);
        else CP_COMMIT();

        const uint32_t st = sbase + (it % NSTAGE) * STAGEB;
#pragma unroll
        for (int ks = 0; ks < 2; ks++) {
            const uint32_t kb = ks * 32;
            uint32_t ah[2][4], bh[8][2];
#pragma unroll
            for (int mi = 0; mi < 2; mi++) {
                const uint32_t ar = st + a_off + mi * (16 * ROWB) + kb;
                LDSM4(ah[mi][0], ah[mi][1], ah[mi][2], ah[mi][3], ar);
            }
#pragma unroll
            for (int ni = 0; ni < 8; ni++) {
                const uint32_t br = st + TILEB + b_off + ni * (8 * ROWB) + kb;
                LDSM2(bh[ni][0], bh[ni][1], br);
            }
#pragma unroll
            for (int mi = 0; mi < 2; mi++)
#pragma unroll
                for (int ni = 0; ni < 8; ni++)
                    MMA16816(acc[mi][ni], ah[mi], bh[ni]);
        }
    }

    const int mrow = m0 + wm * 32 + (lane >> 2);
    const int ncol = n0 + wn * 64 + (lane & 3) * 2;
#pragma unroll
    for (int mi = 0; mi < 2; mi++)
#pragma unroll
        for (int ni = 0; ni < 8; ni++) {
            const int cbase = ncol + ni * 8;
            const float b0 = __ldg(&bias[cbase]);
            const float b1 = __ldg(&bias[cbase + 1]);
            const int r0 = mrow + mi * 16;
            *(float2*)(C + (size_t)r0 * D_ + cbase) =
                make_float2(acc[mi][ni][0] + b0, acc[mi][ni][1] + b1);
            *(float2*)(C + (size_t)(r0 + 8) * D_ + cbase) =
                make_float2(acc[mi][ni][2] + b0, acc[mi][ni][3] + b1);
        }
}

// ---------------- fused hi-only splits: x, Wkv, Wg, Wo + coupling softmax -----
#define SPLIT_X   (M_ * D_ / 4)
#define SPLIT_KV  (2 * D_ * D_ / 4)
#define SPLIT_W   (D_ * D_ / 4)
#define SPLIT_TOT (SPLIT_X + SPLIT_KV + 2 * SPLIT_W)
#define SPLIT_BLKS ((SPLIT_TOT + 255) / 256)

__global__ __launch_bounds__(256)
void fused_split_kernel(const float4* __restrict__ x, const float4* __restrict__ Wkv,
                        const float4* __restrict__ Wg, const float4* __restrict__ Wo,
                        const float* __restrict__ fc)
{
    if (blockIdx.x == SPLIT_BLKS) {
        // coupling softmax: one block, 16 threads active
        const int tid = threadIdx.x;
        if (tid < H_) {
            float row[H_];
            float mx = -1e30f;
#pragma unroll
            for (int j = 0; j < H_; j++) { row[j] = __ldg(&fc[tid * H_ + j]); mx = fmaxf(mx, row[j]); }
            float sum = 0.f;
#pragma unroll
            for (int j = 0; j < H_; j++) { row[j] = __expf(row[j] - mx); sum += row[j]; }
            const float inv = 1.f / sum;
#pragma unroll
            for (int j = 0; j < H_; j++) g_cp[tid * H_ + j] = row[j] * inv;
        }
        return;
    }
    const int i = blockIdx.x * blockDim.x + threadIdx.x;
    if (i >= SPLIT_TOT) return;
    const float4* src;
    __half2* dst;
    int j;
    if (i < SPLIT_X)                          { j = i;                          src = x;   dst = (__half2*)g_xhi; }
    else if (i < SPLIT_X + SPLIT_KV)          { j = i - SPLIT_X;                src = Wkv; dst = (__half2*)g_Wkvhi; }
    else if (i < SPLIT_X + SPLIT_KV + SPLIT_W){ j = i - SPLIT_X - SPLIT_KV;     src = Wg;  dst = (__half2*)g_Wghi; }
    else                                      { j = i - SPLIT_X - SPLIT_KV - SPLIT_W; src = Wo; dst = (__half2*)g_Wohi; }
    const float4 v = src[j];
    dst[2 * j]     = __halves2half2(__float2half(v.x), __float2half(v.y));
    dst[2 * j + 1] = __halves2half2(__float2half(v.z), __float2half(v.w));
}

// ---------------- Weff = Wqs @ Wq (per head), fp32 -> fp16 --------------------
__global__ __launch_bounds__(256)
void weff_kernel(const float* __restrict__ Wqkv, const float* __restrict__ Wqs,
                 __half* __restrict__ Weff)
{
    const int r = blockIdx.y;
    const int k = blockIdx.x * 256 + threadIdx.x;
    float acc = 0.f;
    if (r < 176) {
        const int h = r / 11, s = r % 11;
        const float* wq = Wqkv + (size_t)(h * 64) * D_ + k;
        const float* ws = Wqs + s * HD_;
#pragma unroll 16
        for (int d = 0; d < 64; d++)
            acc = fmaf(__ldg(&ws[d]), __ldg(&wq[(size_t)d * D_]), acc);
    }
    Weff[(size_t)r * D_ + k] = __float2half(acc);
}

// -------- gains: softmax over S logits per (m, h); coalesced writes ----------
__global__ __launch_bounds__(256)
void gains_kernel(const float* __restrict__ logits,
                  const float* __restrict__ scale_gain)
{
    const int idx = blockIdx.x * 256 + threadIdx.x;
    const int m = idx >> 4, h = idx & 15;
    const float* lp = logits + (size_t)m * 256 + h * S_;

    float l[S_];
    float mx = -1e30f;
#pragma unroll
    for (int s = 0; s < S_; s++) {
        l[s] = __ldg(&lp[s]) + __ldg(&scale_gain[s * H_ + h]);
        mx = fmaxf(mx, l[s]);
    }
    float sum = 0.f;
#pragma unroll
    for (int s = 0; s < S_; s++) { l[s] = __expf(l[s] - mx); sum += l[s]; }
    const float inv = 1.f / sum;

    float* gp = g_gains + ((size_t)((m >> 11) * H_ + h) * N_ + (m & (N_ - 1))) * S_;
#pragma unroll
    for (int s = 0; s < S_; s++) gp[s] = l[s] * inv;
}

// -------- stage: causal multiscale dilated D4 conv (fp16 smem slab) -----------
// slab = 2048 x 16 halfs = 64 KB -> 2-3 CTAs/SM. kmag applied at slab load.
// thread owns an hd-pair: hp = t & 7 (hd = hd0 + hp*2), nb = t >> 3 (64 streams)
#define CONV_SMEM (N_ * 16 * 2)   // 65536 B

__global__ __launch_bounds__(512)
void conv_kernel4()
{
    extern __shared__ __half2 slabh[];       // [2048][8] half2
    const int bh  = blockIdx.y;
    const int hd0 = blockIdx.x * 16;
    const int t   = threadIdx.x;
    const int b   = bh >> 4, h = bh & 15;

    // slab load: 2048 n x 32 B = 8192 uint2; apply kmag, store as half2
    const __half* fb = g_vfield + (size_t)bh * N_ * HD_;
#pragma unroll
    for (int i = 0; i < 16; i++) {
        const int idx = i * 512 + t;         // 0..8191
        const int n = idx >> 2, c = idx & 3; // c: which 4-half group in 32B
        const uint2 raw = *(const uint2*)(fb + (size_t)n * HD_ + hd0 + c * 4);
        const float km = __ldg(&g_kmag[((size_t)(b * N_ + n)) * H_ + h]);
        const float2 p0 = __half22float2(*(const __half2*)&raw.x);
        const float2 p1 = __half22float2(*(const __half2*)&raw.y);
        slabh[n * 8 + c * 2]     = __floats2half2_rn(p0.x * km, p0.y * km);
        slabh[n * 8 + c * 2 + 1] = __floats2half2_rn(p1.x * km, p1.y * km);
    }
    __syncthreads();

    const int hp = t & 7;                    // hd pair
    const int nb = t >> 3;                   // 0..63
    __half2* ob = (__half2*)(g_outf + (size_t)b * N_ * D_ + h * HD_ + hd0 + hp * 2);
    for (int ni = 0; ni < 32; ni++) {
        const int n = ni * 64 + nb;
        const float* gp = g_gains + ((size_t)bh * N_ + n) * S_;

        float2 c0 = __half22float2(slabh[n * 8 + hp]);
        float accx = D4_3 * c0.x, accy = D4_3 * c0.y;
#pragma unroll
        for (int j = 0; j < S_; j++) {
            const int d = 1 << j;
            const float g = __ldg(&gp[j]);
            const int s3 = n - 3 * d, s2 = n - 2 * d, s1 = n - d;
            if (s3 >= 0) {
                const float2 v = __half22float2(slabh[s3 * 8 + hp]);
                accx = fmaf(g * D4_0, v.x, accx); accy = fmaf(g * D4_0, v.y, accy);
            }
            if (s2 >= 0) {
                const float2 v = __half22float2(slabh[s2 * 8 + hp]);
                accx = fmaf(g * D4_1, v.x, accx); accy = fmaf(g * D4_1, v.y, accy);
            }
            if (s1 >= 0) {
                const float2 v = __half22float2(slabh[s1 * 8 + hp]);
                accx = fmaf(g * D4_2, v.x, accx); accy = fmaf(g * D4_2, v.y, accy);
            }
        }
        ob[(size_t)n * (D_ / 2)] = __floats2half2_rn(accx, accy);
    }
}

// -------- stage: head coupling + gate; emits fp16 G (precomputed cp) ----------
__global__ __launch_bounds__(256)
void couple_gate_kernel()
{
    __shared__ float sf[D_];
    __shared__ float cps[H_ * H_];

    const int bn = blockIdx.x;
    const int tid = threadIdx.x;

    cps[tid] = g_cp[tid];                     // 256 threads, one coalesced load
    const __half2* orow = (const __half2*)(g_outf + (size_t)bn * D_);
#pragma unroll
    for (int r = 0; r < 2; r++) {
        const int i = tid + r * 256;
        const float2 f = __half22float2(orow[i]);
        sf[2 * i] = f.x; sf[2 * i + 1] = f.y;
    }
    __syncthreads();

    const size_t grow = (size_t)bn * D_;
#pragma unroll
    for (int r = 0; r < 4; r++) {
        const int idx = tid + r * 256;
        const int i = idx >> 6, hd = idx & 63;
        float acc = 0.f;
#pragma unroll
        for (int j = 0; j < H_; j++) acc = fmaf(cps[i * 16 + j], sf[j * HD_ + hd], acc);
        g_Ghi[grow + idx] = __float2half(acc * __half2float(g_gate[grow + idx]));
    }
}

// ------------------------------- launch --------------------------------------
extern "C" void kernel_launch(void* const* d_in, const int* in_sizes, int n_in,
                              void* d_out, int out_size)
{
    const float* x    = (const float*)d_in[0];
    const float* Wqkv = (const float*)d_in[1];
    const float* bqkv = (const float*)d_in[2];
    const float* Wo   = (const float*)d_in[3];
    const float* bo   = (const float*)d_in[4];
    const float* Wg   = (const float*)d_in[5];
    const float* bg   = (const float*)d_in[6];
    const float* scale_gain = (const float*)d_in[7];
    const float* Wqs  = (const float*)d_in[8];
    const float* fc   = (const float*)d_in[9];
    float* out = (float*)d_out;

    float *p_logits, *p_kmag;
    __half *p_gate, *p_xhi, *p_Ghi, *p_Wkvhi, *p_Wghi, *p_Wohi, *p_Weff;
    cudaGetSymbolAddress((void**)&p_gate, g_gate);
    cudaGetSymbolAddress((void**)&p_logits, g_logits);
    cudaGetSymbolAddress((void**)&p_kmag, g_kmag);
    cudaGetSymbolAddress((void**)&p_xhi, g_xhi);
    cudaGetSymbolAddress((void**)&p_Ghi, g_Ghi);
    cudaGetSymbolAddress((void**)&p_Wkvhi, g_Wkvhi);
    cudaGetSymbolAddress((void**)&p_Wghi, g_Wghi);
    cudaGetSymbolAddress((void**)&p_Wohi, g_Wohi);
    cudaGetSymbolAddress((void**)&p_Weff, g_Weffhi);

    cudaFuncSetAttribute(gemm_combo, cudaFuncAttributeMaxDynamicSharedMemorySize, GEMM_SMEM);
    cudaFuncSetAttribute(gemm_out,   cudaFuncAttributeMaxDynamicSharedMemorySize, GEMM_SMEM);
    cudaFuncSetAttribute(conv_kernel4, cudaFuncAttributeMaxDynamicSharedMemorySize, CONV_SMEM);

    // 0) fused hi-only splits (+ coupling softmax block) + Weff precompute
    fused_split_kernel<<<SPLIT_BLKS + 1, 256>>>(
        (const float4*)x, (const float4*)(Wqkv + (size_t)D_ * D_),
        (const float4*)Wg, (const float4*)Wo, fc);
    {
        dim3 wgrid(D_ / 256, 256);
        weff_kernel<<<wgrid, 256>>>(Wqkv, Wqs, p_Weff);
    }

    // 1) mega combo: kmag | gate | logits | v  (all 1-pass, one launch)
    {
        dim3 grid(26, M_ / GBM);
        gemm_combo<<<grid, 256, GEMM_SMEM>>>(
            p_xhi, p_Wkvhi, p_Wghi, p_Weff, p_Wkvhi + (size_t)D_ * D_,
            bqkv + D_, bg, bqkv + 2 * D_,
            p_kmag, p_gate, p_logits);
    }
    // 2) gains softmax
    gains_kernel<<<M_ * H_ / 256, 256>>>(p_logits, scale_gain);

    // 3) multiscale causal conv (fp16 slab, kmag at load) -> outf fp16
    {
        dim3 grid(HD_ / 16, B_ * H_);
        conv_kernel4<<<grid, 512, CONV_SMEM>>>();
    }
    // 4) head coupling + gate -> Ghi (fp16)
    couple_gate_kernel<<<B_ * N_, 256>>>();

    // 5) out = Ghi @ Wohi^T + bo   (1-pass)
    {
        dim3 grid(D_ / GBN, M_ / GBM);
        gemm_out<<<grid, 256, GEMM_SMEM>>>(p_Ghi, p_Wohi, bo, out);
    }
}

// round 14
// speedup vs baseline: 1.0866x; 1.0037x over previous
#include <cuda_runtime.h>
#include <cuda_fp16.h>
#include <math.h>
#include <stdint.h>

// Problem dims (fixed by the reference)
#define B_    4
#define N_    2048
#define D_    1024
#define H_    16
#define HD_   64
#define S_    11
#define M_    (B_ * N_)   // 8192

#define D4_0 0.4829629131445341f
#define D4_1 0.8365163037378079f
#define D4_2 0.2241438680420134f
#define D4_3 (-0.1294095225512604f)

// ---------------- scratch (static device globals; no allocation) -------------
__device__ __align__(256) __half g_gate[M_ * D_];
__device__ __align__(256) float g_logits[M_ * 256];     // h*11+s cols (176 used)
__device__ __align__(256) float g_kmag[M_ * H_];        // [m][h]
__device__ __align__(256) __half g_vfield[B_ * H_ * N_ * HD_]; // raw v, [bh][n][hd]
__device__ __align__(256) float g_gains[B_ * H_ * N_ * S_];    // [bh][n][s]
__device__ __align__(256) __half g_outf [M_ * D_];      // [b][n][h*64+hd]
__device__ __align__(256) float g_cp[H_ * H_];          // softmaxed coupling

__device__ __align__(256) __half g_xhi[M_ * D_];
__device__ __align__(256) __half g_Ghi[M_ * D_];
__device__ __align__(256) __half g_Wkvhi[2 * D_ * D_];  // Wk, Wv hi
__device__ __align__(256) __half g_Wghi[D_ * D_];
__device__ __align__(256) __half g_Wohi[D_ * D_];
__device__ __align__(256) __half g_Weffhi[256 * D_];    // rows h*11+s (r<176), else 0

// ============================ PTX helpers ====================================
__device__ __forceinline__ uint32_t smem_u32(const void* p) {
    uint32_t a;
    asm("{ .reg .u64 t; cvta.to.shared.u64 t, %1; cvt.u32.u64 %0, t; }" : "=r"(a) : "l"(p));
    return a;
}

#define CP_ASYNC_16(sp, gp) \
    asm volatile("cp.async.cg.shared.global [%0], [%1], 16;" :: "r"(sp), "l"(gp) : "memory")
#define CP_COMMIT() asm volatile("cp.async.commit_group;" ::: "memory")
#define CP_WAIT(n)  asm volatile("cp.async.wait_group %0;" :: "n"(n) : "memory")

#define LDSM4(r0, r1, r2, r3, addr) \
    asm volatile("ldmatrix.sync.aligned.m8n8.x4.shared.b16 {%0,%1,%2,%3}, [%4];" \
        : "=r"(r0), "=r"(r1), "=r"(r2), "=r"(r3) : "r"(addr))
#define LDSM2(r0, r1, addr) \
    asm volatile("ldmatrix.sync.aligned.m8n8.x2.shared.b16 {%0,%1}, [%2];" \
        : "=r"(r0), "=r"(r1) : "r"(addr))

#define MMA16816(d, a, b) \
    asm volatile("mma.sync.aligned.m16n8k16.row.col.f32.f16.f16.f32 " \
        "{%0,%1,%2,%3}, {%4,%5,%6,%7}, {%8,%9}, {%0,%1,%2,%3};" \
        : "+f"((d)[0]), "+f"((d)[1]), "+f"((d)[2]), "+f"((d)[3]) \
        : "r"((a)[0]), "r"((a)[1]), "r"((a)[2]), "r"((a)[3]), "r"((b)[0]), "r"((b)[1]))

// ======================= fp16 tensor-core GEMM building blocks ===============
#define GBM 128
#define GBN 128
#define GBK 32
#define NSTAGE 4
#define ROWB   80
#define TILEB  (128 * ROWB)
#define STAGEB (2 * TILEB)
#define GEMM_SMEM (NSTAGE * STAGEB)

// ---- mega combo 1-pass GEMM: kmag | gate | logits | v in one launch ---------
// bx 0..7:   k -> reduce ||k|| per head -> g_kmag
// bx 8..15:  gate = sigmoid(x@Wg^T+bg) -> g_gate (fp16)
// bx 16..17: logits = x@Weff^T -> g_logits
// bx 18..25: v = x@Wv^T+bv -> g_vfield [bh][n][hd] (fp16, no kmag)
__global__ __launch_bounds__(256, 1)
void gemm_combo(const __half* __restrict__ xhi,
                const __half* __restrict__ Wk,
                const __half* __restrict__ Wg,
                const __half* __restrict__ Weff,
                const __half* __restrict__ Wv,
                const float* __restrict__ bk,
                const float* __restrict__ bg,
                const float* __restrict__ bv,
                float* __restrict__ Ckmag, __half* __restrict__ Cgate,
                float* __restrict__ Clog)
{
    constexpr int K = D_;
    extern __shared__ char smx[];
    const uint32_t sbase = smem_u32(smx);
    const int t = threadIdx.x;
    const int wid = t >> 5, lane = t & 31;
    const int wm = wid & 3, wn = wid >> 2;
    const int m0 = blockIdx.y * GBM;
    const int bx = blockIdx.x;

    const __half* Bp;
    if (bx < 8)       Bp = Wk   + (size_t)bx * 128 * K;
    else if (bx < 16) Bp = Wg   + (size_t)(bx - 8) * 128 * K;
    else if (bx < 18) Bp = Weff + (size_t)(bx - 16) * 128 * K;
    else              Bp = Wv   + (size_t)(bx - 18) * 128 * K;

    const int KITERS = K / GBK;

    float acc[2][8][4];
#pragma unroll
    for (int mi = 0; mi < 2; mi++)
#pragma unroll
        for (int ni = 0; ni < 8; ni++)
#pragma unroll
            for (int v = 0; v < 4; v++) acc[mi][ni][v] = 0.f;

    auto load_stage = [&](int stage, int kk) {
        const uint32_t sb = sbase + stage * STAGEB;
        const int r = t >> 2, c = t & 3;
#pragma unroll
        for (int j = 0; j < 4; j++) {
            const int tile = j >> 1;
            const int row  = ((j & 1) << 6) + r;
            const __half* g = (tile == 0) ? xhi : Bp;
            const int grow  = (tile == 0) ? (m0 + row) : row;
            CP_ASYNC_16(sb + tile * TILEB + row * ROWB + c * 16,
                        g + (size_t)grow * K + kk + c * 8);
        }
        CP_COMMIT();
    };

#pragma unroll
    for (int s = 0; s < NSTAGE - 1; s++) load_stage(s, s * GBK);

    const uint32_t a_off = (wm * 32 + (lane & 15)) * ROWB + (lane >> 4) * 16;
    const uint32_t b_off = (wn * 64 + (lane & 7)) * ROWB + ((lane >> 3) & 1) * 16;

    for (int it = 0; it < KITERS; it++) {
        CP_WAIT(NSTAGE - 2);
        __syncthreads();
        const int kload = it + NSTAGE - 1;
        if (kload < KITERS) load_stage(kload % NSTAGE, kload * GBK);
        else CP_COMMIT();                         // keep wait_group accounting exact

        const uint32_t st = sbase + (it % NSTAGE) * STAGEB;
#pragma unroll
        for (int ks = 0; ks < 2; ks++) {
            const uint32_t kb = ks * 32;
            uint32_t ah[2][4], bh[8][2];
#pragma unroll
            for (int mi = 0; mi < 2; mi++) {
                const uint32_t ar = st + a_off + mi * (16 * ROWB) + kb;
                LDSM4(ah[mi][0], ah[mi][1], ah[mi][2], ah[mi][3], ar);
            }
#pragma unroll
            for (int ni = 0; ni < 8; ni++) {
                const uint32_t br = st + TILEB + b_off + ni * (8 * ROWB) + kb;
                LDSM2(bh[ni][0], bh[ni][1], br);
            }
#pragma unroll
            for (int mi = 0; mi < 2; mi++)
#pragma unroll
                for (int ni = 0; ni < 8; ni++)
                    MMA16816(acc[mi][ni], ah[mi], bh[ni]);
        }
    }

    const int mrow = m0 + wm * 32 + (lane >> 2);
    const int ncl  = wn * 64 + (lane & 3) * 2;

    if (bx < 8) {
        // ||k||: this block's 128 cols = heads 2bx, 2bx+1; wn selects head
        float rs[2][2] = {{0.f, 0.f}, {0.f, 0.f}};
#pragma unroll
        for (int mi = 0; mi < 2; mi++)
#pragma unroll
            for (int ni = 0; ni < 8; ni++) {
                const int cl = bx * 128 + ncl + ni * 8;
                const float b0 = __ldg(&bk[cl]);
                const float b1 = __ldg(&bk[cl + 1]);
                const float v0 = acc[mi][ni][0] + b0, v1 = acc[mi][ni][1] + b1;
                const float v2 = acc[mi][ni][2] + b0, v3 = acc[mi][ni][3] + b1;
                rs[mi][0] += v0 * v0 + v1 * v1;
                rs[mi][1] += v2 * v2 + v3 * v3;
            }
#pragma unroll
        for (int mi = 0; mi < 2; mi++)
#pragma unroll
            for (int hf = 0; hf < 2; hf++) {
                rs[mi][hf] += __shfl_xor_sync(0xffffffffu, rs[mi][hf], 1);
                rs[mi][hf] += __shfl_xor_sync(0xffffffffu, rs[mi][hf], 2);
            }
        if ((lane & 3) == 0) {
            const int head = bx * 2 + wn;
#pragma unroll
            for (int mi = 0; mi < 2; mi++) {
                const int r0 = mrow + mi * 16;
                Ckmag[(size_t)r0 * H_ + head]       = sqrtf(rs[mi][0]);
                Ckmag[(size_t)(r0 + 8) * H_ + head] = sqrtf(rs[mi][1]);
            }
        }
    } else if (bx < 16) {
#pragma unroll
        for (int mi = 0; mi < 2; mi++)
#pragma unroll
            for (int ni = 0; ni < 8; ni++) {
                const int cl = (bx - 8) * 128 + ncl + ni * 8;
                const float b0 = __ldg(&bg[cl]);
                const float b1 = __ldg(&bg[cl + 1]);
                float v0 = acc[mi][ni][0] + b0, v1 = acc[mi][ni][1] + b1;
                float v2 = acc[mi][ni][2] + b0, v3 = acc[mi][ni][3] + b1;
                v0 = 1.f / (1.f + __expf(-v0)); v1 = 1.f / (1.f + __expf(-v1));
                v2 = 1.f / (1.f + __expf(-v2)); v3 = 1.f / (1.f + __expf(-v3));
                const int r0 = mrow + mi * 16;
                *(__half2*)(Cgate + (size_t)r0 * D_ + cl)       = __floats2half2_rn(v0, v1);
                *(__half2*)(Cgate + (size_t)(r0 + 8) * D_ + cl) = __floats2half2_rn(v2, v3);
            }
    } else if (bx < 18) {
#pragma unroll
        for (int mi = 0; mi < 2; mi++)
#pragma unroll
            for (int ni = 0; ni < 8; ni++) {
                const int cl = (bx - 16) * 128 + ncl + ni * 8;
                const int r0 = mrow + mi * 16;
                *(float2*)(Clog + (size_t)r0 * 256 + cl) =
                    make_float2(acc[mi][ni][0], acc[mi][ni][1]);
                *(float2*)(Clog + (size_t)(r0 + 8) * 256 + cl) =
                    make_float2(acc[mi][ni][2], acc[mi][ni][3]);
            }
    } else {
        // v region: scatter raw v (+bias) into g_vfield [bh][n][hd] fp16
        const int head = (bx - 18) * 2 + wn;
        const int hdb  = (lane & 3) * 2;
#pragma unroll
        for (int mi = 0; mi < 2; mi++) {
            const int r0 = mrow + mi * 16;
            const int r1 = r0 + 8;
            __half* f0 = g_vfield + (((size_t)((r0 >> 11) * H_ + head) * N_ + (r0 & (N_ - 1))) * HD_);
            __half* f1 = g_vfield + (((size_t)((r1 >> 11) * H_ + head) * N_ + (r1 & (N_ - 1))) * HD_);
#pragma unroll
            for (int ni = 0; ni < 8; ni++) {
                const int hd = hdb + ni * 8;
                const int cg = head * 64 + hd;
                const float b0 = __ldg(&bv[cg]);
                const float b1 = __ldg(&bv[cg + 1]);
                *(__half2*)(f0 + hd) = __floats2half2_rn(acc[mi][ni][0] + b0, acc[mi][ni][1] + b1);
                *(__half2*)(f1 + hd) = __floats2half2_rn(acc[mi][ni][2] + b0, acc[mi][ni][3] + b1);
            }
        }
    }
}

// ---- out GEMM (1-pass): out = Ghi @ Wohi^T + bo ------------------------------
__global__ __launch_bounds__(256, 1)
void gemm_out(const __half* __restrict__ Ahi, const __half* __restrict__ Bhi,
              const float* __restrict__ bias, float* __restrict__ C)
{
    constexpr int K = D_;
    extern __shared__ char smx[];
    const uint32_t sbase = smem_u32(smx);
    const int t = threadIdx.x;
    const int wid = t >> 5, lane = t & 31;
    const int wm = wid & 3, wn = wid >> 2;
    const int m0 = blockIdx.y * GBM;
    const int n0 = blockIdx.x * GBN;
    const int KITERS = K / GBK;

    float acc[2][8][4];
#pragma unroll
    for (int mi = 0; mi < 2; mi++)
#pragma unroll
        for (int ni = 0; ni < 8; ni++)
#pragma unroll
            for (int v = 0; v < 4; v++) acc[mi][ni][v] = 0.f;

    auto load_stage = [&](int stage, int kk) {
        const uint32_t sb = sbase + stage * STAGEB;
        const int r = t >> 2, c = t & 3;
#pragma unroll
        for (int j = 0; j < 4; j++) {
            const int tile = j >> 1;
            const int row  = ((j & 1) << 6) + r;
            const __half* g = (tile == 0) ? Ahi : Bhi;
            const int grow  = (tile == 0) ? (m0 + row) : (n0 + row);
            CP_ASYNC_16(sb + tile * TILEB + row * ROWB + c * 16,
                        g + (size_t)grow * K + kk + c * 8);
        }
        CP_COMMIT();
    };

#pragma unroll
    for (int s = 0; s < NSTAGE - 1; s++) load_stage(s, s * GBK);

    const uint32_t a_off = (wm * 32 + (lane & 15)) * ROWB + (lane >> 4) * 16;
    const uint32_t b_off = (wn * 64 + (lane & 7)) * ROWB + ((lane >> 3) & 1) * 16;

    for (int it = 0; it < KITERS; it++) {
        CP_WAIT(NSTAGE - 2);
        __syncthreads();
        const int kload = it + NSTAGE - 1;
        if (kload < KITERS) load_stage(kload % NSTAGE, kload * GBK);
        else CP_COMMIT();

        const uint32_t st = sbase + (it % NSTAGE) * STAGEB;
#pragma unroll
        for (int ks = 0; ks < 2; ks++) {
            const uint32_t kb = ks * 32;
            uint32_t ah[2][4], bh[8][2];
#pragma unroll
            for (int mi = 0; mi < 2; mi++) {
                const uint32_t ar = st + a_off + mi * (16 * ROWB) + kb;
                LDSM4(ah[mi][0], ah[mi][1], ah[mi][2], ah[mi][3], ar);
            }
#pragma unroll
            for (int ni = 0; ni < 8; ni++) {
                const uint32_t br = st + TILEB + b_off + ni * (8 * ROWB) + kb;
                LDSM2(bh[ni][0], bh[ni][1], br);
            }
#pragma unroll
            for (int mi = 0; mi < 2; mi++)
#pragma unroll
                for (int ni = 0; ni < 8; ni++)
                    MMA16816(acc[mi][ni], ah[mi], bh[ni]);
        }
    }

    const int mrow = m0 + wm * 32 + (lane >> 2);
    const int ncol = n0 + wn * 64 + (lane & 3) * 2;
#pragma unroll
    for (int mi = 0; mi < 2; mi++)
#pragma unroll
        for (int ni = 0; ni < 8; ni++) {
            const int cbase = ncol + ni * 8;
            const float b0 = __ldg(&bias[cbase]);
            const float b1 = __ldg(&bias[cbase + 1]);
            const int r0 = mrow + mi * 16;
            *(float2*)(C + (size_t)r0 * D_ + cbase) =
                make_float2(acc[mi][ni][0] + b0, acc[mi][ni][1] + b1);
            *(float2*)(C + (size_t)(r0 + 8) * D_ + cbase) =
                make_float2(acc[mi][ni][2] + b0, acc[mi][ni][3] + b1);
        }
}

// ---------------- fused hi-only splits (vectorized) + coupling softmax --------
// float4 units: x 2097152 | Wkv 524288 | Wg 262144 | Wo 262144 ; all /4
#define SPLIT_X   (M_ * D_ / 4)
#define SPLIT_KV  (2 * D_ * D_ / 4)
#define SPLIT_W   (D_ * D_ / 4)
#define SPLIT_TOT (SPLIT_X + SPLIT_KV + 2 * SPLIT_W)
#define SPLIT_QUADS (SPLIT_TOT / 4)          // 786432
#define SPLIT_BLKS  (SPLIT_QUADS / 256)      // 3072

__global__ __launch_bounds__(256)
void fused_split_kernel(const float4* __restrict__ x, const float4* __restrict__ Wkv,
                        const float4* __restrict__ Wg, const float4* __restrict__ Wo,
                        const float* __restrict__ fc)
{
    if (blockIdx.x == SPLIT_BLKS) {
        // coupling softmax: one block, 16 threads active
        const int tid = threadIdx.x;
        if (tid < H_) {
            float row[H_];
            float mx = -1e30f;
#pragma unroll
            for (int j = 0; j < H_; j++) { row[j] = __ldg(&fc[tid * H_ + j]); mx = fmaxf(mx, row[j]); }
            float sum = 0.f;
#pragma unroll
            for (int j = 0; j < H_; j++) { row[j] = __expf(row[j] - mx); sum += row[j]; }
            const float inv = 1.f / sum;
#pragma unroll
            for (int j = 0; j < H_; j++) g_cp[tid * H_ + j] = row[j] * inv;
        }
        return;
    }
    const int i  = blockIdx.x * 256 + threadIdx.x;   // 0..SPLIT_QUADS-1
    const int j0 = i * 4;                            // first float4 index
    const float4* src;
    __half* dst;
    int j;
    if (j0 < SPLIT_X)                           { j = j0;                           src = x;   dst = g_xhi; }
    else if (j0 < SPLIT_X + SPLIT_KV)           { j = j0 - SPLIT_X;                 src = Wkv; dst = g_Wkvhi; }
    else if (j0 < SPLIT_X + SPLIT_KV + SPLIT_W) { j = j0 - SPLIT_X - SPLIT_KV;      src = Wg;  dst = g_Wghi; }
    else                                        { j = j0 - SPLIT_X - SPLIT_KV - SPLIT_W; src = Wo; dst = g_Wohi; }

    // 4 x float4 in (64 B), 2 x uint4 out (32 B)
    __half h[16];
#pragma unroll
    for (int q = 0; q < 4; q++) {
        const float4 v = src[j + q];
        h[q * 4 + 0] = __float2half(v.x); h[q * 4 + 1] = __float2half(v.y);
        h[q * 4 + 2] = __float2half(v.z); h[q * 4 + 3] = __float2half(v.w);
    }
    *(uint4*)(dst + (size_t)j * 4)     = *(const uint4*)(h);
    *(uint4*)(dst + (size_t)j * 4 + 8) = *(const uint4*)(h + 8);
}

// ---------------- Weff = Wqs @ Wq (per head), fp32 -> fp16 --------------------
__global__ __launch_bounds__(256)
void weff_kernel(const float* __restrict__ Wqkv, const float* __restrict__ Wqs,
                 __half* __restrict__ Weff)
{
    const int r = blockIdx.y;
    const int k = blockIdx.x * 256 + threadIdx.x;
    float acc = 0.f;
    if (r < 176) {
        const int h = r / 11, s = r % 11;
        const float* wq = Wqkv + (size_t)(h * 64) * D_ + k;
        const float* ws = Wqs + s * HD_;
#pragma unroll 16
        for (int d = 0; d < 64; d++)
            acc = fmaf(__ldg(&ws[d]), __ldg(&wq[(size_t)d * D_]), acc);
    }
    Weff[(size_t)r * D_ + k] = __float2half(acc);
}

// -------- gains: softmax over S logits per (m, h); write-coalesced mapping ----
__global__ __launch_bounds__(256)
void gains_kernel(const float* __restrict__ logits,
                  const float* __restrict__ scale_gain)
{
    const int t  = threadIdx.x;
    const int ml = t & 15;                    // m within block
    const int h  = t >> 4;                    // consecutive 16 threads share h
    const int m  = blockIdx.x * 16 + ml;
    const float* lp = logits + (size_t)m * 256 + h * S_;

    float l[S_];
    float mx = -1e30f;
#pragma unroll
    for (int s = 0; s < S_; s++) {
        l[s] = __ldg(&lp[s]) + __ldg(&scale_gain[s * H_ + h]);
        mx = fmaxf(mx, l[s]);
    }
    float sum = 0.f;
#pragma unroll
    for (int s = 0; s < S_; s++) { l[s] = __expf(l[s] - mx); sum += l[s]; }
    const float inv = 1.f / sum;

    float* gp = g_gains + ((size_t)((m >> 11) * H_ + h) * N_ + (m & (N_ - 1))) * S_;
#pragma unroll
    for (int s = 0; s < S_; s++) gp[s] = l[s] * inv;
}

// -------- stage: causal multiscale dilated D4 conv (fp16 smem slab) -----------
#define CONV_SMEM (N_ * 16 * 2)   // 65536 B

__global__ __launch_bounds__(512)
void conv_kernel4()
{
    extern __shared__ __half2 slabh[];       // [2048][8] half2
    const int bh  = blockIdx.y;
    const int hd0 = blockIdx.x * 16;
    const int t   = threadIdx.x;
    const int b   = bh >> 4, h = bh & 15;

    const __half* fb = g_vfield + (size_t)bh * N_ * HD_;
#pragma unroll
    for (int i = 0; i < 16; i++) {
        const int idx = i * 512 + t;         // 0..8191
        const int n = idx >> 2, c = idx & 3;
        const uint2 raw = *(const uint2*)(fb + (size_t)n * HD_ + hd0 + c * 4);
        const float km = __ldg(&g_kmag[((size_t)(b * N_ + n)) * H_ + h]);
        const float2 p0 = __half22float2(*(const __half2*)&raw.x);
        const float2 p1 = __half22float2(*(const __half2*)&raw.y);
        slabh[n * 8 + c * 2]     = __floats2half2_rn(p0.x * km, p0.y * km);
        slabh[n * 8 + c * 2 + 1] = __floats2half2_rn(p1.x * km, p1.y * km);
    }
    __syncthreads();

    const int hp = t & 7;
    const int nb = t >> 3;
    __half2* ob = (__half2*)(g_outf + (size_t)b * N_ * D_ + h * HD_ + hd0 + hp * 2);
    for (int ni = 0; ni < 32; ni++) {
        const int n = ni * 64 + nb;
        const float* gp = g_gains + ((size_t)bh * N_ + n) * S_;

        float2 c0 = __half22float2(slabh[n * 8 + hp]);
        float accx = D4_3 * c0.x, accy = D4_3 * c0.y;
#pragma unroll
        for (int j = 0; j < S_; j++) {
            const int d = 1 << j;
            const float g = __ldg(&gp[j]);
            const int s3 = n - 3 * d, s2 = n - 2 * d, s1 = n - d;
            if (s3 >= 0) {
                const float2 v = __half22float2(slabh[s3 * 8 + hp]);
                accx = fmaf(g * D4_0, v.x, accx); accy = fmaf(g * D4_0, v.y, accy);
            }
            if (s2 >= 0) {
                const float2 v = __half22float2(slabh[s2 * 8 + hp]);
                accx = fmaf(g * D4_1, v.x, accx); accy = fmaf(g * D4_1, v.y, accy);
            }
            if (s1 >= 0) {
                const float2 v = __half22float2(slabh[s1 * 8 + hp]);
                accx = fmaf(g * D4_2, v.x, accx); accy = fmaf(g * D4_2, v.y, accy);
            }
        }
        ob[(size_t)n * (D_ / 2)] = __floats2half2_rn(accx, accy);
    }
}

// -------- stage: head coupling + gate; emits fp16 G (precomputed cp) ----------
__global__ __launch_bounds__(256)
void couple_gate_kernel()
{
    __shared__ float sf[D_];
    __shared__ float cps[H_ * H_];

    const int bn = blockIdx.x;
    const int tid = threadIdx.x;

    cps[tid] = g_cp[tid];
    const __half2* orow = (const __half2*)(g_outf + (size_t)bn * D_);
#pragma unroll
    for (int r = 0; r < 2; r++) {
        const int i = tid + r * 256;
        const float2 f = __half22float2(orow[i]);
        sf[2 * i] = f.x; sf[2 * i + 1] = f.y;
    }
    __syncthreads();

    const size_t grow = (size_t)bn * D_;
#pragma unroll
    for (int r = 0; r < 4; r++) {
        const int idx = tid + r * 256;
        const int i = idx >> 6, hd = idx & 63;
        float acc = 0.f;
#pragma unroll
        for (int j = 0; j < H_; j++) acc = fmaf(cps[i * 16 + j], sf[j * HD_ + hd], acc);
        g_Ghi[grow + idx] = __float2half(acc * __half2float(g_gate[grow + idx]));
    }
}

// ------------------------------- launch --------------------------------------
extern "C" void kernel_launch(void* const* d_in, const int* in_sizes, int n_in,
                              void* d_out, int out_size)
{
    const float* x    = (const float*)d_in[0];
    const float* Wqkv = (const float*)d_in[1];
    const float* bqkv = (const float*)d_in[2];
    const float* Wo   = (const float*)d_in[3];
    const float* bo   = (const float*)d_in[4];
    const float* Wg   = (const float*)d_in[5];
    const float* bg   = (const float*)d_in[6];
    const float* scale_gain = (const float*)d_in[7];
    const float* Wqs  = (const float*)d_in[8];
    const float* fc   = (const float*)d_in[9];
    float* out = (float*)d_out;

    float *p_logits, *p_kmag;
    __half *p_gate, *p_xhi, *p_Ghi, *p_Wkvhi, *p_Wghi, *p_Wohi, *p_Weff;
    cudaGetSymbolAddress((void**)&p_gate, g_gate);
    cudaGetSymbolAddress((void**)&p_logits, g_logits);
    cudaGetSymbolAddress((void**)&p_kmag, g_kmag);
    cudaGetSymbolAddress((void**)&p_xhi, g_xhi);
    cudaGetSymbolAddress((void**)&p_Ghi, g_Ghi);
    cudaGetSymbolAddress((void**)&p_Wkvhi, g_Wkvhi);
    cudaGetSymbolAddress((void**)&p_Wghi, g_Wghi);
    cudaGetSymbolAddress((void**)&p_Wohi, g_Wohi);
    cudaGetSymbolAddress((void**)&p_Weff, g_Weffhi);

    cudaFuncSetAttribute(gemm_combo, cudaFuncAttributeMaxDynamicSharedMemorySize, GEMM_SMEM);
    cudaFuncSetAttribute(gemm_out,   cudaFuncAttributeMaxDynamicSharedMemorySize, GEMM_SMEM);
    cudaFuncSetAttribute(conv_kernel4, cudaFuncAttributeMaxDynamicSharedMemorySize, CONV_SMEM);

    // 0) fused hi-only splits (vectorized) + coupling softmax + Weff
    fused_split_kernel<<<SPLIT_BLKS + 1, 256>>>(
        (const float4*)x, (const float4*)(Wqkv + (size_t)D_ * D_),
        (const float4*)Wg, (const float4*)Wo, fc);
    {
        dim3 wgrid(D_ / 256, 256);
        weff_kernel<<<wgrid, 256>>>(Wqkv, Wqs, p_Weff);
    }

    // 1) mega combo: kmag | gate | logits | v  (all 1-pass, one launch)
    {
        dim3 grid(26, M_ / GBM);
        gemm_combo<<<grid, 256, GEMM_SMEM>>>(
            p_xhi, p_Wkvhi, p_Wghi, p_Weff, p_Wkvhi + (size_t)D_ * D_,
            bqkv + D_, bg, bqkv + 2 * D_,
            p_kmag, p_gate, p_logits);
    }
    // 2) gains softmax (write-coalesced mapping)
    gains_kernel<<<M_ / 16, 256>>>(p_logits, scale_gain);

    // 3) multiscale causal conv (fp16 slab, kmag at load) -> outf fp16
    {
        dim3 grid(HD_ / 16, B_ * H_);
        conv_kernel4<<<grid, 512, CONV_SMEM>>>();
    }
    // 4) head coupling + gate -> Ghi (fp16)
    couple_gate_kernel<<<B_ * N_, 256>>>();

    // 5) out = Ghi @ Wohi^T + bo   (1-pass)
    {
        dim3 grid(D_ / GBN, M_ / GBM);
        gemm_out<<<grid, 256, GEMM_SMEM>>>(p_Ghi, p_Wohi, bo, out);
    }
}

// round 15
// speedup vs baseline: 1.1016x; 1.0138x over previous
#include <cuda_runtime.h>
#include <cuda_fp16.h>
#include <math.h>
#include <stdint.h>

// Problem dims (fixed by the reference)
#define B_    4
#define N_    2048
#define D_    1024
#define H_    16
#define HD_   64
#define S_    11
#define M_    (B_ * N_)   // 8192

#define D4_0 0.4829629131445341f
#define D4_1 0.8365163037378079f
#define D4_2 0.2241438680420134f
#define D4_3 (-0.1294095225512604f)

// ---------------- scratch (static device globals; no allocation) -------------
__device__ __align__(256) __half g_gate[M_ * D_];
__device__ __align__(256) float g_logits[M_ * 256];     // h*11+s cols (176 used)
__device__ __align__(256) float g_kmag[M_ * H_];        // [m][h]
__device__ __align__(256) __half g_vfield[B_ * H_ * N_ * HD_]; // raw v, [bh][n][hd]
__device__ __align__(256) float g_gains[B_ * H_ * N_ * S_];    // [bh][n][s]
__device__ __align__(256) __half g_outf [M_ * D_];      // [b][n][h*64+hd]
__device__ __align__(256) float g_cp[H_ * H_];          // softmaxed coupling

__device__ __align__(256) __half g_xhi[M_ * D_];
__device__ __align__(256) __half g_Ghi[M_ * D_];
__device__ __align__(256) __half g_Wkvhi[2 * D_ * D_];  // Wk, Wv hi
__device__ __align__(256) __half g_Wghi[D_ * D_];
__device__ __align__(256) __half g_Wohi[D_ * D_];
__device__ __align__(256) __half g_Weffhi[256 * D_];    // rows h*11+s (r<176), else 0

// ============================ PTX helpers ====================================
__device__ __forceinline__ uint32_t smem_u32(const void* p) {
    uint32_t a;
    asm("{ .reg .u64 t; cvta.to.shared.u64 t, %1; cvt.u32.u64 %0, t; }" : "=r"(a) : "l"(p));
    return a;
}

#define CP_ASYNC_16(sp, gp) \
    asm volatile("cp.async.cg.shared.global [%0], [%1], 16;" :: "r"(sp), "l"(gp) : "memory")
#define CP_COMMIT() asm volatile("cp.async.commit_group;" ::: "memory")
#define CP_WAIT(n)  asm volatile("cp.async.wait_group %0;" :: "n"(n) : "memory")

#define LDSM4(r0, r1, r2, r3, addr) \
    asm volatile("ldmatrix.sync.aligned.m8n8.x4.shared.b16 {%0,%1,%2,%3}, [%4];" \
        : "=r"(r0), "=r"(r1), "=r"(r2), "=r"(r3) : "r"(addr))
#define LDSM2(r0, r1, addr) \
    asm volatile("ldmatrix.sync.aligned.m8n8.x2.shared.b16 {%0,%1}, [%2];" \
        : "=r"(r0), "=r"(r1) : "r"(addr))

#define MMA16816(d, a, b) \
    asm volatile("mma.sync.aligned.m16n8k16.row.col.f32.f16.f16.f32 " \
        "{%0,%1,%2,%3}, {%4,%5,%6,%7}, {%8,%9}, {%0,%1,%2,%3};" \
        : "+f"((d)[0]), "+f"((d)[1]), "+f"((d)[2]), "+f"((d)[3]) \
        : "r"((a)[0]), "r"((a)[1]), "r"((a)[2]), "r"((a)[3]), "r"((b)[0]), "r"((b)[1]))

// ======================= fp16 tensor-core GEMM building blocks ===============
#define GBM 128
#define GBN 128
#define GBK 32
#define NSTAGE 4
#define ROWB   80
#define TILEB  (128 * ROWB)
#define STAGEB (2 * TILEB)
#define GEMM_SMEM (NSTAGE * STAGEB)

// ---- mega combo 1-pass GEMM: kmag | gate | logits | v in one launch ---------
// bx 0..7:   k -> reduce ||k|| per head -> g_kmag
// bx 8..15:  gate = sigmoid(x@Wg^T+bg) -> g_gate (fp16)
// bx 16..17: logits = x@Weff^T -> g_logits
// bx 18..25: v = x@Wv^T+bv -> g_vfield [bh][n][hd] (fp16, no kmag)
__global__ __launch_bounds__(256, 1)
void gemm_combo(const __half* __restrict__ xhi,
                const __half* __restrict__ Wk,
                const __half* __restrict__ Wg,
                const __half* __restrict__ Weff,
                const __half* __restrict__ Wv,
                const float* __restrict__ bk,
                const float* __restrict__ bg,
                const float* __restrict__ bv,
                float* __restrict__ Ckmag, __half* __restrict__ Cgate,
                float* __restrict__ Clog)
{
    constexpr int K = D_;
    extern __shared__ char smx[];
    const uint32_t sbase = smem_u32(smx);
    const int t = threadIdx.x;
    const int wid = t >> 5, lane = t & 31;
    const int wm = wid & 3, wn = wid >> 2;
    const int m0 = blockIdx.y * GBM;
    const int bx = blockIdx.x;

    const __half* Bp;
    if (bx < 8)       Bp = Wk   + (size_t)bx * 128 * K;
    else if (bx < 16) Bp = Wg   + (size_t)(bx - 8) * 128 * K;
    else if (bx < 18) Bp = Weff + (size_t)(bx - 16) * 128 * K;
    else              Bp = Wv   + (size_t)(bx - 18) * 128 * K;

    const int KITERS = K / GBK;

    float acc[2][8][4];
#pragma unroll
    for (int mi = 0; mi < 2; mi++)
#pragma unroll
        for (int ni = 0; ni < 8; ni++)
#pragma unroll
            for (int v = 0; v < 4; v++) acc[mi][ni][v] = 0.f;

    auto load_stage = [&](int stage, int kk) {
        const uint32_t sb = sbase + stage * STAGEB;
        const int r = t >> 2, c = t & 3;
#pragma unroll
        for (int j = 0; j < 4; j++) {
            const int tile = j >> 1;
            const int row  = ((j & 1) << 6) + r;
            const __half* g = (tile == 0) ? xhi : Bp;
            const int grow  = (tile == 0) ? (m0 + row) : row;
            CP_ASYNC_16(sb + tile * TILEB + row * ROWB + c * 16,
                        g + (size_t)grow * K + kk + c * 8);
        }
        CP_COMMIT();
    };

#pragma unroll
    for (int s = 0; s < NSTAGE - 1; s++) load_stage(s, s * GBK);

    const uint32_t a_off = (wm * 32 + (lane & 15)) * ROWB + (lane >> 4) * 16;
    const uint32_t b_off = (wn * 64 + (lane & 7)) * ROWB + ((lane >> 3) & 1) * 16;

    for (int it = 0; it < KITERS; it++) {
        CP_WAIT(NSTAGE - 2);
        __syncthreads();
        const int kload = it + NSTAGE - 1;
        if (kload < KITERS) load_stage(kload % NSTAGE, kload * GBK);
        else CP_COMMIT();                         // keep wait_group accounting exact

        const uint32_t st = sbase + (it % NSTAGE) * STAGEB;
#pragma unroll
        for (int ks = 0; ks < 2; ks++) {
            const uint32_t kb = ks * 32;
            uint32_t ah[2][4], bh[8][2];
#pragma unroll
            for (int mi = 0; mi < 2; mi++) {
                const uint32_t ar = st + a_off + mi * (16 * ROWB) + kb;
                LDSM4(ah[mi][0], ah[mi][1], ah[mi][2], ah[mi][3], ar);
            }
#pragma unroll
            for (int ni = 0; ni < 8; ni++) {
                const uint32_t br = st + TILEB + b_off + ni * (8 * ROWB) + kb;
                LDSM2(bh[ni][0], bh[ni][1], br);
            }
#pragma unroll
            for (int mi = 0; mi < 2; mi++)
#pragma unroll
                for (int ni = 0; ni < 8; ni++)
                    MMA16816(acc[mi][ni], ah[mi], bh[ni]);
        }
    }

    const int mrow = m0 + wm * 32 + (lane >> 2);
    const int ncl  = wn * 64 + (lane & 3) * 2;

    if (bx < 8) {
        // ||k||: this block's 128 cols = heads 2bx, 2bx+1; wn selects head
        float rs[2][2] = {{0.f, 0.f}, {0.f, 0.f}};
#pragma unroll
        for (int mi = 0; mi < 2; mi++)
#pragma unroll
            for (int ni = 0; ni < 8; ni++) {
                const int cl = bx * 128 + ncl + ni * 8;
                const float b0 = __ldg(&bk[cl]);
                const float b1 = __ldg(&bk[cl + 1]);
                const float v0 = acc[mi][ni][0] + b0, v1 = acc[mi][ni][1] + b1;
                const float v2 = acc[mi][ni][2] + b0, v3 = acc[mi][ni][3] + b1;
                rs[mi][0] += v0 * v0 + v1 * v1;
                rs[mi][1] += v2 * v2 + v3 * v3;
            }
#pragma unroll
        for (int mi = 0; mi < 2; mi++)
#pragma unroll
            for (int hf = 0; hf < 2; hf++) {
                rs[mi][hf] += __shfl_xor_sync(0xffffffffu, rs[mi][hf], 1);
                rs[mi][hf] += __shfl_xor_sync(0xffffffffu, rs[mi][hf], 2);
            }
        if ((lane & 3) == 0) {
            const int head = bx * 2 + wn;
#pragma unroll
            for (int mi = 0; mi < 2; mi++) {
                const int r0 = mrow + mi * 16;
                Ckmag[(size_t)r0 * H_ + head]       = sqrtf(rs[mi][0]);
                Ckmag[(size_t)(r0 + 8) * H_ + head] = sqrtf(rs[mi][1]);
            }
        }
    } else if (bx < 16) {
#pragma unroll
        for (int mi = 0; mi < 2; mi++)
#pragma unroll
            for (int ni = 0; ni < 8; ni++) {
                const int cl = (bx - 8) * 128 + ncl + ni * 8;
                const float b0 = __ldg(&bg[cl]);
                const float b1 = __ldg(&bg[cl + 1]);
                float v0 = acc[mi][ni][0] + b0, v1 = acc[mi][ni][1] + b1;
                float v2 = acc[mi][ni][2] + b0, v3 = acc[mi][ni][3] + b1;
                v0 = 1.f / (1.f + __expf(-v0)); v1 = 1.f / (1.f + __expf(-v1));
                v2 = 1.f / (1.f + __expf(-v2)); v3 = 1.f / (1.f + __expf(-v3));
                const int r0 = mrow + mi * 16;
                *(__half2*)(Cgate + (size_t)r0 * D_ + cl)       = __floats2half2_rn(v0, v1);
                *(__half2*)(Cgate + (size_t)(r0 + 8) * D_ + cl) = __floats2half2_rn(v2, v3);
            }
    } else if (bx < 18) {
#pragma unroll
        for (int mi = 0; mi < 2; mi++)
#pragma unroll
            for (int ni = 0; ni < 8; ni++) {
                const int cl = (bx - 16) * 128 + ncl + ni * 8;
                const int r0 = mrow + mi * 16;
                *(float2*)(Clog + (size_t)r0 * 256 + cl) =
                    make_float2(acc[mi][ni][0], acc[mi][ni][1]);
                *(float2*)(Clog + (size_t)(r0 + 8) * 256 + cl) =
                    make_float2(acc[mi][ni][2], acc[mi][ni][3]);
            }
    } else {
        // v region: scatter raw v (+bias) into g_vfield [bh][n][hd] fp16
        const int head = (bx - 18) * 2 + wn;
        const int hdb  = (lane & 3) * 2;
#pragma unroll
        for (int mi = 0; mi < 2; mi++) {
            const int r0 = mrow + mi * 16;
            const int r1 = r0 + 8;
            __half* f0 = g_vfield + (((size_t)((r0 >> 11) * H_ + head) * N_ + (r0 & (N_ - 1))) * HD_);
            __half* f1 = g_vfield + (((size_t)((r1 >> 11) * H_ + head) * N_ + (r1 & (N_ - 1))) * HD_);
#pragma unroll
            for (int ni = 0; ni < 8; ni++) {
                const int hd = hdb + ni * 8;
                const int cg = head * 64 + hd;
                const float b0 = __ldg(&bv[cg]);
                const float b1 = __ldg(&bv[cg + 1]);
                *(__half2*)(f0 + hd) = __floats2half2_rn(acc[mi][ni][0] + b0, acc[mi][ni][1] + b1);
                *(__half2*)(f1 + hd) = __floats2half2_rn(acc[mi][ni][2] + b0, acc[mi][ni][3] + b1);
            }
        }
    }
}

// ---- out GEMM (1-pass): out = Ghi @ Wohi^T + bo ------------------------------
__global__ __launch_bounds__(256, 1)
void gemm_out(const __half* __restrict__ Ahi, const __half* __restrict__ Bhi,
              const float* __restrict__ bias, float* __restrict__ C)
{
    constexpr int K = D_;
    extern __shared__ char smx[];
    const uint32_t sbase = smem_u32(smx);
    const int t = threadIdx.x;
    const int wid = t >> 5, lane = t & 31;
    const int wm = wid & 3, wn = wid >> 2;
    const int m0 = blockIdx.y * GBM;
    const int n0 = blockIdx.x * GBN;
    const int KITERS = K / GBK;

    float acc[2][8][4];
#pragma unroll
    for (int mi = 0; mi < 2; mi++)
#pragma unroll
        for (int ni = 0; ni < 8; ni++)
#pragma unroll
            for (int v = 0; v < 4; v++) acc[mi][ni][v] = 0.f;

    auto load_stage = [&](int stage, int kk) {
        const uint32_t sb = sbase + stage * STAGEB;
        const int r = t >> 2, c = t & 3;
#pragma unroll
        for (int j = 0; j < 4; j++) {
            const int tile = j >> 1;
            const int row  = ((j & 1) << 6) + r;
            const __half* g = (tile == 0) ? Ahi : Bhi;
            const int grow  = (tile == 0) ? (m0 + row) : (n0 + row);
            CP_ASYNC_16(sb + tile * TILEB + row * ROWB + c * 16,
                        g + (size_t)grow * K + kk + c * 8);
        }
        CP_COMMIT();
    };

#pragma unroll
    for (int s = 0; s < NSTAGE - 1; s++) load_stage(s, s * GBK);

    const uint32_t a_off = (wm * 32 + (lane & 15)) * ROWB + (lane >> 4) * 16;
    const uint32_t b_off = (wn * 64 + (lane & 7)) * ROWB + ((lane >> 3) & 1) * 16;

    for (int it = 0; it < KITERS; it++) {
        CP_WAIT(NSTAGE - 2);
        __syncthreads();
        const int kload = it + NSTAGE - 1;
        if (kload < KITERS) load_stage(kload % NSTAGE, kload * GBK);
        else CP_COMMIT();

        const uint32_t st = sbase + (it % NSTAGE) * STAGEB;
#pragma unroll
        for (int ks = 0; ks < 2; ks++) {
            const uint32_t kb = ks * 32;
            uint32_t ah[2][4], bh[8][2];
#pragma unroll
            for (int mi = 0; mi < 2; mi++) {
                const uint32_t ar = st + a_off + mi * (16 * ROWB) + kb;
                LDSM4(ah[mi][0], ah[mi][1], ah[mi][2], ah[mi][3], ar);
            }
#pragma unroll
            for (int ni = 0; ni < 8; ni++) {
                const uint32_t br = st + TILEB + b_off + ni * (8 * ROWB) + kb;
                LDSM2(bh[ni][0], bh[ni][1], br);
            }
#pragma unroll
            for (int mi = 0; mi < 2; mi++)
#pragma unroll
                for (int ni = 0; ni < 8; ni++)
                    MMA16816(acc[mi][ni], ah[mi], bh[ni]);
        }
    }

    const int mrow = m0 + wm * 32 + (lane >> 2);
    const int ncol = n0 + wn * 64 + (lane & 3) * 2;
#pragma unroll
    for (int mi = 0; mi < 2; mi++)
#pragma unroll
        for (int ni = 0; ni < 8; ni++) {
            const int cbase = ncol + ni * 8;
            const float b0 = __ldg(&bias[cbase]);
            const float b1 = __ldg(&bias[cbase + 1]);
            const int r0 = mrow + mi * 16;
            *(float2*)(C + (size_t)r0 * D_ + cbase) =
                make_float2(acc[mi][ni][0] + b0, acc[mi][ni][1] + b1);
            *(float2*)(C + (size_t)(r0 + 8) * D_ + cbase) =
                make_float2(acc[mi][ni][2] + b0, acc[mi][ni][3] + b1);
        }
}

// ---------------- fused hi-only splits (vectorized) + coupling softmax --------
#define SPLIT_X   (M_ * D_ / 4)
#define SPLIT_KV  (2 * D_ * D_ / 4)
#define SPLIT_W   (D_ * D_ / 4)
#define SPLIT_TOT (SPLIT_X + SPLIT_KV + 2 * SPLIT_W)
#define SPLIT_QUADS (SPLIT_TOT / 4)          // 786432
#define SPLIT_BLKS  (SPLIT_QUADS / 256)      // 3072

__global__ __launch_bounds__(256)
void fused_split_kernel(const float4* __restrict__ x, const float4* __restrict__ Wkv,
                        const float4* __restrict__ Wg, const float4* __restrict__ Wo,
                        const float* __restrict__ fc)
{
    if (blockIdx.x == SPLIT_BLKS) {
        const int tid = threadIdx.x;
        if (tid < H_) {
            float row[H_];
            float mx = -1e30f;
#pragma unroll
            for (int j = 0; j < H_; j++) { row[j] = __ldg(&fc[tid * H_ + j]); mx = fmaxf(mx, row[j]); }
            float sum = 0.f;
#pragma unroll
            for (int j = 0; j < H_; j++) { row[j] = __expf(row[j] - mx); sum += row[j]; }
            const float inv = 1.f / sum;
#pragma unroll
            for (int j = 0; j < H_; j++) g_cp[tid * H_ + j] = row[j] * inv;
        }
        return;
    }
    const int i  = blockIdx.x * 256 + threadIdx.x;
    const int j0 = i * 4;
    const float4* src;
    __half* dst;
    int j;
    if (j0 < SPLIT_X)                           { j = j0;                           src = x;   dst = g_xhi; }
    else if (j0 < SPLIT_X + SPLIT_KV)           { j = j0 - SPLIT_X;                 src = Wkv; dst = g_Wkvhi; }
    else if (j0 < SPLIT_X + SPLIT_KV + SPLIT_W) { j = j0 - SPLIT_X - SPLIT_KV;      src = Wg;  dst = g_Wghi; }
    else                                        { j = j0 - SPLIT_X - SPLIT_KV - SPLIT_W; src = Wo; dst = g_Wohi; }

    __half h[16];
#pragma unroll
    for (int q = 0; q < 4; q++) {
        const float4 v = src[j + q];
        h[q * 4 + 0] = __float2half(v.x); h[q * 4 + 1] = __float2half(v.y);
        h[q * 4 + 2] = __float2half(v.z); h[q * 4 + 3] = __float2half(v.w);
    }
    *(uint4*)(dst + (size_t)j * 4)     = *(const uint4*)(h);
    *(uint4*)(dst + (size_t)j * 4 + 8) = *(const uint4*)(h + 8);
}

// ---------------- Weff = Wqs @ Wq (per head), fp32 -> fp16 --------------------
__global__ __launch_bounds__(256)
void weff_kernel(const float* __restrict__ Wqkv, const float* __restrict__ Wqs,
                 __half* __restrict__ Weff)
{
    const int r = blockIdx.y;
    const int k = blockIdx.x * 256 + threadIdx.x;
    float acc = 0.f;
    if (r < 176) {
        const int h = r / 11, s = r % 11;
        const float* wq = Wqkv + (size_t)(h * 64) * D_ + k;
        const float* ws = Wqs + s * HD_;
#pragma unroll 16
        for (int d = 0; d < 64; d++)
            acc = fmaf(__ldg(&ws[d]), __ldg(&wq[(size_t)d * D_]), acc);
    }
    Weff[(size_t)r * D_ + k] = __float2half(acc);
}

// -------- gains: softmax over S logits per (m, h); write-coalesced mapping ----
__global__ __launch_bounds__(256)
void gains_kernel(const float* __restrict__ logits,
                  const float* __restrict__ scale_gain)
{
    const int t  = threadIdx.x;
    const int ml = t & 15;
    const int h  = t >> 4;
    const int m  = blockIdx.x * 16 + ml;
    const float* lp = logits + (size_t)m * 256 + h * S_;

    float l[S_];
    float mx = -1e30f;
#pragma unroll
    for (int s = 0; s < S_; s++) {
        l[s] = __ldg(&lp[s]) + __ldg(&scale_gain[s * H_ + h]);
        mx = fmaxf(mx, l[s]);
    }
    float sum = 0.f;
#pragma unroll
    for (int s = 0; s < S_; s++) { l[s] = __expf(l[s] - mx); sum += l[s]; }
    const float inv = 1.f / sum;

    float* gp = g_gains + ((size_t)((m >> 11) * H_ + h) * N_ + (m & (N_ - 1))) * S_;
#pragma unroll
    for (int s = 0; s < S_; s++) gp[s] = l[s] * inv;
}

// -------- stage: causal multiscale dilated D4 conv (fp16 slab, n-owner) -------
// slab rows padded to 9 half2 (18 halves) -> conflict-free (9 coprime 32); 72 KB
// thread owns whole n-rows: n = t + i*512, loads gains ONCE per n (coalesced)
#define CONV_SMEM (N_ * 18 * 2)   // 73728 B

__global__ __launch_bounds__(512)
void conv_kernel5()
{
    extern __shared__ __half2 slabh[];       // [2048][9] half2 (8 used + pad)
    const int bh  = blockIdx.y;
    const int hd0 = blockIdx.x * 16;
    const int t   = threadIdx.x;
    const int b   = bh >> 4, h = bh & 15;

    // slab load: apply kmag, store rows of 8 half2 (+1 pad)
    const __half* fb = g_vfield + (size_t)bh * N_ * HD_;
#pragma unroll
    for (int i = 0; i < 16; i++) {
        const int idx = i * 512 + t;         // 0..8191
        const int n = idx >> 2, c = idx & 3;
        const uint2 raw = *(const uint2*)(fb + (size_t)n * HD_ + hd0 + c * 4);
        const float km = __ldg(&g_kmag[((size_t)(b * N_ + n)) * H_ + h]);
        const float2 p0 = __half22float2(*(const __half2*)&raw.x);
        const float2 p1 = __half22float2(*(const __half2*)&raw.y);
        slabh[n * 9 + c * 2]     = __floats2half2_rn(p0.x * km, p0.y * km);
        slabh[n * 9 + c * 2 + 1] = __floats2half2_rn(p1.x * km, p1.y * km);
    }
    __syncthreads();

    for (int i = 0; i < 4; i++) {
        const int n = i * 512 + t;
        const float* gp = g_gains + ((size_t)bh * N_ + n) * S_;
        float g[S_];
#pragma unroll
        for (int s = 0; s < S_; s++) g[s] = __ldg(&gp[s]);   // 44 B/n, warp-coalesced

        float2 acc[8];
#pragma unroll
        for (int p = 0; p < 8; p++) {
            const float2 v = __half22float2(slabh[n * 9 + p]);
            acc[p].x = D4_3 * v.x; acc[p].y = D4_3 * v.y;
        }
#pragma unroll
        for (int j = 0; j < S_; j++) {
            const int d = 1 << j;
            const int s3 = n - 3 * d, s2 = n - 2 * d, s1 = n - d;
            if (s3 >= 0) {
                const float w = g[j] * D4_0;
#pragma unroll
                for (int p = 0; p < 8; p++) {
                    const float2 v = __half22float2(slabh[s3 * 9 + p]);
                    acc[p].x = fmaf(w, v.x, acc[p].x); acc[p].y = fmaf(w, v.y, acc[p].y);
                }
            }
            if (s2 >= 0) {
                const float w = g[j] * D4_1;
#pragma unroll
                for (int p = 0; p < 8; p++) {
                    const float2 v = __half22float2(slabh[s2 * 9 + p]);
                    acc[p].x = fmaf(w, v.x, acc[p].x); acc[p].y = fmaf(w, v.y, acc[p].y);
                }
            }
            if (s1 >= 0) {
                const float w = g[j] * D4_2;
#pragma unroll
                for (int p = 0; p < 8; p++) {
                    const float2 v = __half22float2(slabh[s1 * 9 + p]);
                    acc[p].x = fmaf(w, v.x, acc[p].x); acc[p].y = fmaf(w, v.y, acc[p].y);
                }
            }
        }
        // write 16 halves (32 B aligned) for this n
        __half hbuf[16];
#pragma unroll
        for (int p = 0; p < 8; p++)
            *(__half2*)(hbuf + p * 2) = __floats2half2_rn(acc[p].x, acc[p].y);
        __half* ob = g_outf + (size_t)b * N_ * D_ + (size_t)n * D_ + h * HD_ + hd0;
        *(uint4*)(ob)     = *(const uint4*)(hbuf);
        *(uint4*)(ob + 8) = *(const uint4*)(hbuf + 8);
    }
}

// -------- stage: head coupling + gate; emits fp16 G (precomputed cp) ----------
__global__ __launch_bounds__(256)
void couple_gate_kernel()
{
    __shared__ float sf[D_];
    __shared__ float cps[H_ * H_];

    const int bn = blockIdx.x;
    const int tid = threadIdx.x;

    cps[tid] = g_cp[tid];
    const __half2* orow = (const __half2*)(g_outf + (size_t)bn * D_);
#pragma unroll
    for (int r = 0; r < 2; r++) {
        const int i = tid + r * 256;
        const float2 f = __half22float2(orow[i]);
        sf[2 * i] = f.x; sf[2 * i + 1] = f.y;
    }
    __syncthreads();

    const size_t grow = (size_t)bn * D_;
#pragma unroll
    for (int r = 0; r < 4; r++) {
        const int idx = tid + r * 256;
        const int i = idx >> 6, hd = idx & 63;
        float acc = 0.f;
#pragma unroll
        for (int j = 0; j < H_; j++) acc = fmaf(cps[i * 16 + j], sf[j * HD_ + hd], acc);
        g_Ghi[grow + idx] = __float2half(acc * __half2float(g_gate[grow + idx]));
    }
}

// ------------------------------- launch --------------------------------------
extern "C" void kernel_launch(void* const* d_in, const int* in_sizes, int n_in,
                              void* d_out, int out_size)
{
    const float* x    = (const float*)d_in[0];
    const float* Wqkv = (const float*)d_in[1];
    const float* bqkv = (const float*)d_in[2];
    const float* Wo   = (const float*)d_in[3];
    const float* bo   = (const float*)d_in[4];
    const float* Wg   = (const float*)d_in[5];
    const float* bg   = (const float*)d_in[6];
    const float* scale_gain = (const float*)d_in[7];
    const float* Wqs  = (const float*)d_in[8];
    const float* fc   = (const float*)d_in[9];
    float* out = (float*)d_out;

    float *p_logits, *p_kmag;
    __half *p_gate, *p_xhi, *p_Ghi, *p_Wkvhi, *p_Wghi, *p_Wohi, *p_Weff;
    cudaGetSymbolAddress((void**)&p_gate, g_gate);
    cudaGetSymbolAddress((void**)&p_logits, g_logits);
    cudaGetSymbolAddress((void**)&p_kmag, g_kmag);
    cudaGetSymbolAddress((void**)&p_xhi, g_xhi);
    cudaGetSymbolAddress((void**)&p_Ghi, g_Ghi);
    cudaGetSymbolAddress((void**)&p_Wkvhi, g_Wkvhi);
    cudaGetSymbolAddress((void**)&p_Wghi, g_Wghi);
    cudaGetSymbolAddress((void**)&p_Wohi, g_Wohi);
    cudaGetSymbolAddress((void**)&p_Weff, g_Weffhi);

    cudaFuncSetAttribute(gemm_combo, cudaFuncAttributeMaxDynamicSharedMemorySize, GEMM_SMEM);
    cudaFuncSetAttribute(gemm_out,   cudaFuncAttributeMaxDynamicSharedMemorySize, GEMM_SMEM);
    cudaFuncSetAttribute(conv_kernel5, cudaFuncAttributeMaxDynamicSharedMemorySize, CONV_SMEM);

    // 0) fused hi-only splits (vectorized) + coupling softmax + Weff
    fused_split_kernel<<<SPLIT_BLKS + 1, 256>>>(
        (const float4*)x, (const float4*)(Wqkv + (size_t)D_ * D_),
        (const float4*)Wg, (const float4*)Wo, fc);
    {
        dim3 wgrid(D_ / 256, 256);
        weff_kernel<<<wgrid, 256>>>(Wqkv, Wqs, p_Weff);
    }

    // 1) mega combo: kmag | gate | logits | v  (all 1-pass, one launch)
    {
        dim3 grid(26, M_ / GBM);
        gemm_combo<<<grid, 256, GEMM_SMEM>>>(
            p_xhi, p_Wkvhi, p_Wghi, p_Weff, p_Wkvhi + (size_t)D_ * D_,
            bqkv + D_, bg, bqkv + 2 * D_,
            p_kmag, p_gate, p_logits);
    }
    // 2) gains softmax
    gains_kernel<<<M_ / 16, 256>>>(p_logits, scale_gain);

    // 3) multiscale causal conv (fp16 slab, n-owner threads) -> outf fp16
    {
        dim3 grid(HD_ / 16, B_ * H_);
        conv_kernel5<<<grid, 512, CONV_SMEM>>>();
    }
    // 4) head coupling + gate -> Ghi (fp16)
    couple_gate_kernel<<<B_ * N_, 256>>>();

    // 5) out = Ghi @ Wohi^T + bo   (1-pass)
    {
        dim3 grid(D_ / GBN, M_ / GBM);
        gemm_out<<<grid, 256, GEMM_SMEM>>>(p_Ghi, p_Wohi, bo, out);
    }
}